// round 5
// baseline (speedup 1.0000x reference)
#include <cuda_runtime.h>
#include <math.h>

#define D 56
#define H 501
#define T 277
#define O 76
#define B 256
#define H3 1503
#define NBLK 128
#define NTHR 256
#define KC 32
#define BM 64
#define BN 16   /* per gate */

// ---------------- static device scratch (no allocations allowed) ----------------
__device__ float d_hin[B * D];
__device__ float d_g0[B * H3];
__device__ float d_ysA[T * B * H];     // 142 MB
__device__ float d_ysB[T * B * H];     // 142 MB
__device__ float d_gbuf[T * B * H3];   // 426 MB (reused for g1 then g2)

// ---------------- grid barrier ----------------
__device__ unsigned int g_arrive = 0;
__device__ volatile unsigned int g_gen = 0;

__device__ __forceinline__ void grid_sync() {
    __syncthreads();
    if (threadIdx.x == 0) {
        __threadfence();
        unsigned int gen = g_gen;
        if (atomicAdd(&g_arrive, 1u) == (unsigned)(NBLK - 1)) {
            g_arrive = 0;
            __threadfence();
            g_gen = gen + 1;
        } else {
            while (g_gen == gen) { }
        }
        __threadfence();
    }
    __syncthreads();
}

// ---------------- packed f32x2 helpers ----------------
__device__ __forceinline__ unsigned long long dup_f32(float x) {
    unsigned long long r;
    unsigned int u = __float_as_uint(x);
    asm("mov.b64 %0, {%1, %1};" : "=l"(r) : "r"(u));
    return r;
}
__device__ __forceinline__ unsigned long long ffma2(unsigned long long a,
                                                    unsigned long long b,
                                                    unsigned long long c) {
    unsigned long long d;
    asm("fma.rn.f32x2 %0, %1, %2, %3;" : "=l"(d) : "l"(a), "l"(b), "l"(c));
    return d;
}
__device__ __forceinline__ float2 unpack2(unsigned long long v) {
    unsigned int lo, hi;
    asm("mov.b64 {%0, %1}, %2;" : "=r"(lo), "=r"(hi) : "l"(v));
    return make_float2(__uint_as_float(lo), __uint_as_float(hi));
}

// ---------------- shared memory ----------------
struct SMemG {
    float hs[KC][BM + 2];        // k-major h tile (pad 2 keeps 8B align + fewer conflicts)
    float ws[3][KC][BN + 1];     // 3-gate W tile
};
union SMem {
    SMemG g;
    float rows[8][H + 1];        // fc2 staging
};

// ---------------- fused 3-gate tile GEMM: acc[g] = hsrc(m0:m0+64,:) . W[g*H+n0+j,:] ----------------
__device__ __forceinline__ void tile3(SMem& sm, const float* __restrict__ hsrc,
                                      const float* __restrict__ W,
                                      int m0, int n0, unsigned long long acc[3][2]) {
    const int tid = threadIdx.x;
    const int tx = tid & 15;
    const int mrow = (tid >> 4) * 4;
    acc[0][0] = acc[0][1] = acc[1][0] = acc[1][1] = acc[2][0] = acc[2][1] = 0ull;
    if (hsrc == nullptr) return;  // h == 0 -> hg == 0 (uniform across block)

    const int lm = tid >> 5;   // 0..7
    const int lk = tid & 31;

    for (int k0 = 0; k0 < H; k0 += KC) {
        // stage h tile (k-major)
#pragma unroll
        for (int i = 0; i < 8; i++) {
            int mm = lm + i * 8;
            int k = k0 + lk;
            float v = (k < H) ? hsrc[(m0 + mm) * H + k] : 0.f;
            sm.g.hs[lk][mm] = v;
        }
        // stage 3-gate W tile
#pragma unroll
        for (int i = 0; i < 6; i++) {
            int e = tid + i * NTHR;
            int g = e >> 9;
            int rem = e & 511;
            int j = rem >> 5;
            int kk = rem & 31;
            int n = n0 + j;
            int k = k0 + kk;
            float v = (n < H && k < H) ? W[(g * H + n) * H + k] : 0.f;
            sm.g.ws[g][kk][j] = v;
        }
        __syncthreads();
#pragma unroll
        for (int kk = 0; kk < KC; kk++) {
            unsigned long long hp0 = *(const unsigned long long*)&sm.g.hs[kk][mrow];
            unsigned long long hp1 = *(const unsigned long long*)&sm.g.hs[kk][mrow + 2];
            unsigned long long w0 = dup_f32(sm.g.ws[0][kk][tx]);
            unsigned long long w1 = dup_f32(sm.g.ws[1][kk][tx]);
            unsigned long long w2 = dup_f32(sm.g.ws[2][kk][tx]);
            acc[0][0] = ffma2(hp0, w0, acc[0][0]);
            acc[0][1] = ffma2(hp1, w0, acc[0][1]);
            acc[1][0] = ffma2(hp0, w1, acc[1][0]);
            acc[1][1] = ffma2(hp1, w1, acc[1][1]);
            acc[2][0] = ffma2(hp0, w2, acc[2][0]);
            acc[2][1] = ffma2(hp1, w2, acc[2][1]);
        }
        __syncthreads();
    }
}

// ---------------- one GRU timestep (all 128 blocks, one tile each) ----------------
__device__ void scan_step(SMem& sm, const float* __restrict__ hprev,
                          const float* __restrict__ g,
                          const float* __restrict__ Whh,
                          const float* __restrict__ bhh,
                          float* __restrict__ hout) {
    const int tile = blockIdx.x;   // 0..127 = 4 M-tiles x 32 N-tiles
    const int mt = tile >> 5;
    const int nt = tile & 31;
    const int m0 = mt * BM;
    const int n0 = nt * BN;

    unsigned long long acc[3][2];
    tile3(sm, hprev, Whh, m0, n0, acc);

    const int tx = threadIdx.x & 15;
    const int ty = threadIdx.x >> 4;
    const int n = n0 + tx;
    if (n < H) {
        const float br = bhh[n];
        const float bz = bhh[H + n];
        const float bn = bhh[2 * H + n];
        float2 r0 = unpack2(acc[0][0]), r1 = unpack2(acc[0][1]);
        float2 z0 = unpack2(acc[1][0]), z1 = unpack2(acc[1][1]);
        float2 n0v = unpack2(acc[2][0]), n1v = unpack2(acc[2][1]);
        float ar[4] = {r0.x, r0.y, r1.x, r1.y};
        float az[4] = {z0.x, z0.y, z1.x, z1.y};
        float an[4] = {n0v.x, n0v.y, n1v.x, n1v.y};
#pragma unroll
        for (int i = 0; i < 4; i++) {
            const int m = m0 + ty * 4 + i;
            const float hp = hprev ? hprev[m * H + n] : 0.f;
            const float* gr = g + m * H3;
            float r = 1.f / (1.f + __expf(-(gr[n] + ar[i] + br)));
            float z = 1.f / (1.f + __expf(-(gr[H + n] + az[i] + bz)));
            float nn = tanhf(gr[2 * H + n] + r * (an[i] + bn));
            hout[m * H + n] = (1.f - z) * nn + z * hp;
        }
    }
}

// ---------------- batched input-gate GEMM: G(M x 3H) = Y(M x H) . Wih^T + bih ----------------
__device__ void gate_gemm(SMem& sm, const float* __restrict__ Y,
                          const float* __restrict__ Wih,
                          const float* __restrict__ bih,
                          float* __restrict__ G, int M) {
    const int Mtiles = M / BM;
    const int total = Mtiles * 32;
    for (int tile = blockIdx.x; tile < total; tile += NBLK) {
        const int mt = tile >> 5;
        const int nt = tile & 31;
        const int m0 = mt * BM;
        const int n0 = nt * BN;

        unsigned long long acc[3][2];
        tile3(sm, Y, Wih, m0, n0, acc);

        const int tx = threadIdx.x & 15;
        const int ty = threadIdx.x >> 4;
        const int n = n0 + tx;
        if (n < H) {
#pragma unroll
            for (int g = 0; g < 3; g++) {
                float2 p0 = unpack2(acc[g][0]);
                float2 p1 = unpack2(acc[g][1]);
                float a[4] = {p0.x, p0.y, p1.x, p1.y};
                const float bb = bih[g * H + n];
#pragma unroll
                for (int i = 0; i < 4; i++) {
                    const int m = m0 + ty * 4 + i;
                    G[m * H3 + g * H + n] = a[i] + bb;
                }
            }
        }
    }
}

// ---------------- fc2 + permute to (B, O, T) ----------------
__device__ void fc2_phase(SMem& sm, const float* __restrict__ Y,
                          const float* __restrict__ W,
                          const float* __restrict__ bias,
                          float* __restrict__ out) {
    const int wid = threadIdx.x >> 5;
    const int lane = threadIdx.x & 31;
    const int M = T * B;
    for (int base = blockIdx.x * 8; base < M; base += NBLK * 8) {
        const int row = base + wid;
        if (row < M) {
            for (int k = lane; k < H; k += 32) sm.rows[wid][k] = Y[row * H + k];
            __syncwarp();
            const int t = row / B;
            const int b = row % B;
            for (int o = lane; o < O; o += 32) {
                float acc = bias[o];
                const float* w = W + o * H;
                for (int k = 0; k < H; k++) acc += sm.rows[wid][k] * w[k];
                out[(b * O + o) * T + t] = acc;
            }
            __syncwarp();
        }
    }
}

// ---------------- persistent mega-kernel ----------------
__global__ void __launch_bounds__(NTHR) decoder_kernel(
    const float* __restrict__ x,
    const float* __restrict__ fc1_w, const float* __restrict__ fc1_b,
    const float* __restrict__ w_ih0, const float* __restrict__ w_hh0,
    const float* __restrict__ b_ih0, const float* __restrict__ b_hh0,
    const float* __restrict__ w_ih1, const float* __restrict__ w_hh1,
    const float* __restrict__ b_ih1, const float* __restrict__ b_hh1,
    const float* __restrict__ w_ih2, const float* __restrict__ w_hh2,
    const float* __restrict__ b_ih2, const float* __restrict__ b_hh2,
    const float* __restrict__ fc2_w, const float* __restrict__ fc2_b,
    float* __restrict__ out) {
    __shared__ SMem sm;
    const int gt = blockIdx.x * NTHR + threadIdx.x;
    const int GT = NBLK * NTHR;

    // fc1 + relu
    for (int i = gt; i < B * D; i += GT) {
        const int b = i / D, d = i % D;
        float acc = fc1_b[d];
        for (int k = 0; k < D; k++) acc += x[b * D + k] * fc1_w[d * D + k];
        d_hin[i] = fmaxf(acc, 0.f);
    }
    grid_sync();

    // g0 = h_in @ w_ih0^T + b_ih0 (constant over t)
    for (int i = gt; i < B * H3; i += GT) {
        const int b = i / H3, j = i % H3;
        float acc = b_ih0[j];
        for (int k = 0; k < D; k++) acc += d_hin[b * D + k] * w_ih0[j * D + k];
        d_g0[i] = acc;
    }
    grid_sync();

    // layer 0 scan -> ysA
    for (int t = 0; t < T; t++) {
        scan_step(sm, t ? d_ysA + (t - 1) * B * H : nullptr, d_g0, w_hh0, b_hh0,
                  d_ysA + t * B * H);
        grid_sync();
    }

    // g1 = ysA @ w_ih1^T + b_ih1
    gate_gemm(sm, d_ysA, w_ih1, b_ih1, d_gbuf, T * B);
    grid_sync();

    // layer 1 scan -> ysB
    for (int t = 0; t < T; t++) {
        scan_step(sm, t ? d_ysB + (t - 1) * B * H : nullptr, d_gbuf + t * B * H3,
                  w_hh1, b_hh1, d_ysB + t * B * H);
        grid_sync();
    }

    // g2 = ysB @ w_ih2^T + b_ih2 (reuse gbuf)
    gate_gemm(sm, d_ysB, w_ih2, b_ih2, d_gbuf, T * B);
    grid_sync();

    // layer 2 scan -> ysA (reused)
    for (int t = 0; t < T; t++) {
        scan_step(sm, t ? d_ysA + (t - 1) * B * H : nullptr, d_gbuf + t * B * H3,
                  w_hh2, b_hh2, d_ysA + t * B * H);
        grid_sync();
    }

    // fc2 + permute
    fc2_phase(sm, d_ysA, fc2_w, fc2_b, out);
}

extern "C" void kernel_launch(void* const* d_in, const int* in_sizes, int n_in,
                              void* d_out, int out_size) {
    const float* x     = (const float*)d_in[0];
    const float* fc1_w = (const float*)d_in[1];
    const float* fc1_b = (const float*)d_in[2];
    const float* w_ih0 = (const float*)d_in[3];
    const float* w_hh0 = (const float*)d_in[4];
    const float* b_ih0 = (const float*)d_in[5];
    const float* b_hh0 = (const float*)d_in[6];
    const float* w_ih1 = (const float*)d_in[7];
    const float* w_hh1 = (const float*)d_in[8];
    const float* b_ih1 = (const float*)d_in[9];
    const float* b_hh1 = (const float*)d_in[10];
    const float* w_ih2 = (const float*)d_in[11];
    const float* w_hh2 = (const float*)d_in[12];
    const float* b_ih2 = (const float*)d_in[13];
    const float* b_hh2 = (const float*)d_in[14];
    const float* fc2_w = (const float*)d_in[15];
    const float* fc2_b = (const float*)d_in[16];
    float* out = (float*)d_out;

    decoder_kernel<<<NBLK, NTHR>>>(x, fc1_w, fc1_b,
                                   w_ih0, w_hh0, b_ih0, b_hh0,
                                   w_ih1, w_hh1, b_ih1, b_hh1,
                                   w_ih2, w_hh2, b_ih2, b_hh2,
                                   fc2_w, fc2_b, out);
}

// round 6
// speedup vs baseline: 1.0525x; 1.0525x over previous
#include <cuda_runtime.h>
#include <math.h>

#define D 56
#define H 501
#define T 277
#define O 76
#define B 256
#define H3 1503
#define NBLK 128
#define NTHR 256
#define KC 32
#define NCHUNK 16          /* ceil(501/32) = 16, K padded to 512 */
#define KPAD 512
#define BM 64
#define BN 16              /* per gate */
#define WS_STRIDE 518      /* 518 mod 32 = 6 -> conflict-free LDS.64 across 16 n-threads */
#define HS_STRIDE 34
#define HSOFF (48 * WS_STRIDE)
#define BUFSZ (BM * HS_STRIDE)
#define SMEM_BYTES ((HSOFF + 2 * BUFSZ) * 4)

typedef unsigned long long ull;

extern __shared__ float sdyn[];

// ---------------- static device scratch ----------------
__device__ float d_hin[B * D];
__device__ float d_g0[B * H3];
__device__ float d_ysA[T * B * H];
__device__ float d_ysB[T * B * H];
__device__ float d_gbuf[(long)T * B * H3];

// ---------------- grid barrier ----------------
__device__ unsigned int g_arrive = 0;
__device__ volatile unsigned int g_gen = 0;

__device__ __forceinline__ void grid_sync() {
    __syncthreads();
    if (threadIdx.x == 0) {
        __threadfence();
        unsigned int gen = g_gen;
        if (atomicAdd(&g_arrive, 1u) == (unsigned)(NBLK - 1)) {
            g_arrive = 0;
            __threadfence();
            g_gen = gen + 1;
        } else {
            while (g_gen == gen) { }
        }
        __threadfence();
    }
    __syncthreads();
}

// ---------------- packed f32x2 helpers ----------------
__device__ __forceinline__ ull ffma2(ull a, ull b, ull c) {
    ull d;
    asm("fma.rn.f32x2 %0, %1, %2, %3;" : "=l"(d) : "l"(a), "l"(b), "l"(c));
    return d;
}
__device__ __forceinline__ float psum(ull v) {
    unsigned int lo, hi;
    asm("mov.b64 {%0, %1}, %2;" : "=r"(lo), "=r"(hi) : "l"(v));
    return __uint_as_float(lo) + __uint_as_float(hi);
}

// ---------------- persistent 3-gate W tile load (once per layer) ----------------
__device__ void load_W(const float* __restrict__ W, int n0) {
    for (int idx = threadIdx.x; idx < 48 * KPAD; idx += NTHR) {
        const int r = idx >> 9;          // row 0..47 = g*16 + j
        const int k = idx & (KPAD - 1);
        const int g = r >> 4;
        const int n = n0 + (r & 15);
        float v = 0.f;
        if (k < H && n < H) v = W[(g * H + n) * H + k];
        sdyn[r * WS_STRIDE + k] = v;
    }
}

// ---------------- h-chunk staging ----------------
__device__ __forceinline__ void prefetch8(float pre[8], const float* __restrict__ src,
                                          int m0, int k0) {
    const int lk = threadIdx.x & 31;
    const int lm = threadIdx.x >> 5;
    const int k = k0 + lk;
#pragma unroll
    for (int i = 0; i < 8; i++) {
        const int mm = lm + i * 8;
        pre[i] = (k < H) ? src[(long)(m0 + mm) * H + k] : 0.f;
    }
}
__device__ __forceinline__ void commit8(float* buf, const float pre[8]) {
    const int lk = threadIdx.x & 31;
    const int lm = threadIdx.x >> 5;
#pragma unroll
    for (int i = 0; i < 8; i++) buf[(lm + i * 8) * HS_STRIDE + lk] = pre[i];
}

// ---------------- 64x48 tile GEMM vs resident W: acc[g*4+i] over k pairs ----------------
__device__ __forceinline__ void tile_compute(const float* __restrict__ src, int m0,
                                             ull acc[12]) {
    const int tx = threadIdx.x & 15;
    const int mrow = (threadIdx.x >> 4) << 2;
    const float* w0p = sdyn + (0 * 16 + tx) * WS_STRIDE;
    const float* w1p = sdyn + (1 * 16 + tx) * WS_STRIDE;
    const float* w2p = sdyn + (2 * 16 + tx) * WS_STRIDE;
    float* hsb = sdyn + HSOFF;

    float pre[8];
    prefetch8(pre, src, m0, 0);
    commit8(hsb, pre);
    __syncthreads();

#pragma unroll 1
    for (int c = 0; c < NCHUNK; c++) {
        if (c + 1 < NCHUNK) prefetch8(pre, src, m0, (c + 1) * KC);
        const float* buf = hsb + (c & 1) * BUFSZ + mrow * HS_STRIDE;
        const int cb = c * KC;
#pragma unroll
        for (int p = 0; p < 16; p++) {
            const ull hp0 = *(const ull*)(buf + 0 * HS_STRIDE + 2 * p);
            const ull hp1 = *(const ull*)(buf + 1 * HS_STRIDE + 2 * p);
            const ull hp2 = *(const ull*)(buf + 2 * HS_STRIDE + 2 * p);
            const ull hp3 = *(const ull*)(buf + 3 * HS_STRIDE + 2 * p);
            const ull w0 = *(const ull*)(w0p + cb + 2 * p);
            const ull w1 = *(const ull*)(w1p + cb + 2 * p);
            const ull w2 = *(const ull*)(w2p + cb + 2 * p);
            acc[0] = ffma2(hp0, w0, acc[0]);
            acc[1] = ffma2(hp1, w0, acc[1]);
            acc[2] = ffma2(hp2, w0, acc[2]);
            acc[3] = ffma2(hp3, w0, acc[3]);
            acc[4] = ffma2(hp0, w1, acc[4]);
            acc[5] = ffma2(hp1, w1, acc[5]);
            acc[6] = ffma2(hp2, w1, acc[6]);
            acc[7] = ffma2(hp3, w1, acc[7]);
            acc[8] = ffma2(hp0, w2, acc[8]);
            acc[9] = ffma2(hp1, w2, acc[9]);
            acc[10] = ffma2(hp2, w2, acc[10]);
            acc[11] = ffma2(hp3, w2, acc[11]);
        }
        if (c + 1 < NCHUNK) {
            commit8(hsb + ((c + 1) & 1) * BUFSZ, pre);
            __syncthreads();
        }
    }
}

// ---------------- scan of one GRU layer (W resident across all timesteps) ----------------
__device__ void scan_layer(const float* __restrict__ gsrc, long gstep,
                           const float* __restrict__ Whh,
                           const float* __restrict__ bhh,
                           float* __restrict__ ybuf) {
    const int mt = blockIdx.x >> 5;
    const int nt = blockIdx.x & 31;
    const int m0 = mt * BM;
    const int n0 = nt * BN;
    const int tx = threadIdx.x & 15;
    const int mrow = (threadIdx.x >> 4) << 2;
    const int n = n0 + tx;

    load_W(Whh, n0);
    __syncthreads();

    float br = 0.f, bz = 0.f, bnn = 0.f;
    if (n < H) { br = bhh[n]; bz = bhh[H + n]; bnn = bhh[2 * H + n]; }

    for (int t = 0; t < T; t++) {
        const float* hprev = t ? ybuf + (long)(t - 1) * B * H : nullptr;
        ull acc[12];
#pragma unroll
        for (int i = 0; i < 12; i++) acc[i] = 0ull;
        if (hprev) tile_compute(hprev, m0, acc);

        if (n < H) {
            const float* gt = gsrc + (long)t * gstep;
#pragma unroll
            for (int i = 0; i < 4; i++) {
                const int m = m0 + mrow + i;
                const float ar = psum(acc[i]);
                const float az = psum(acc[4 + i]);
                const float an = psum(acc[8 + i]);
                const float hp = hprev ? hprev[(long)m * H + n] : 0.f;
                const float* gr = gt + (long)m * H3;
                const float r = 1.f / (1.f + __expf(-(gr[n] + ar + br)));
                const float z = 1.f / (1.f + __expf(-(gr[H + n] + az + bz)));
                const float nn = tanhf(gr[2 * H + n] + r * (an + bnn));
                ybuf[(long)t * B * H + (long)m * H + n] = (1.f - z) * nn + z * hp;
            }
        }
        grid_sync();
    }
}

// ---------------- batched input-gate GEMM (W resident across all M tiles) ----------------
__device__ void gate_layer(const float* __restrict__ Y,
                           const float* __restrict__ Wih,
                           const float* __restrict__ bih,
                           float* __restrict__ G) {
    const int nt = blockIdx.x & 31;
    const int n0 = nt * BN;
    const int tx = threadIdx.x & 15;
    const int mrow = (threadIdx.x >> 4) << 2;
    const int n = n0 + tx;
    const int MT = (T * B) / BM;   // 1108

    load_W(Wih, n0);
    __syncthreads();

    for (int mt = blockIdx.x >> 5; mt < MT; mt += 4) {
        const int m0 = mt * BM;
        ull acc[12];
#pragma unroll
        for (int i = 0; i < 12; i++) acc[i] = 0ull;
        tile_compute(Y, m0, acc);

        if (n < H) {
#pragma unroll
            for (int g = 0; g < 3; g++) {
                const float bb = bih[g * H + n];
#pragma unroll
                for (int i = 0; i < 4; i++) {
                    G[(long)(m0 + mrow + i) * H3 + g * H + n] = psum(acc[g * 4 + i]) + bb;
                }
            }
        }
    }
}

// ---------------- fc2 + permute to (B, O, T) ----------------
__device__ void fc2_phase(const float* __restrict__ Y,
                          const float* __restrict__ W,
                          const float* __restrict__ bias,
                          float* __restrict__ out) {
    const int wid = threadIdx.x >> 5;
    const int lane = threadIdx.x & 31;
    const int M = T * B;
    float* rows = sdyn;   // 8 rows of 502 floats
    for (int base = blockIdx.x * 8; base < M; base += NBLK * 8) {
        const int row = base + wid;
        if (row < M) {
            for (int k = lane; k < H; k += 32) rows[wid * 502 + k] = Y[(long)row * H + k];
            __syncwarp();
            const int t = row / B;
            const int b = row % B;
            for (int o = lane; o < O; o += 32) {
                float acc = bias[o];
                const float* w = W + o * H;
                for (int k = 0; k < H; k++) acc += rows[wid * 502 + k] * w[k];
                out[((long)b * O + o) * T + t] = acc;
            }
            __syncwarp();
        }
    }
}

// ---------------- persistent mega-kernel ----------------
__global__ void __launch_bounds__(NTHR, 1) decoder_kernel(
    const float* __restrict__ x,
    const float* __restrict__ fc1_w, const float* __restrict__ fc1_b,
    const float* __restrict__ w_ih0, const float* __restrict__ w_hh0,
    const float* __restrict__ b_ih0, const float* __restrict__ b_hh0,
    const float* __restrict__ w_ih1, const float* __restrict__ w_hh1,
    const float* __restrict__ b_ih1, const float* __restrict__ b_hh1,
    const float* __restrict__ w_ih2, const float* __restrict__ w_hh2,
    const float* __restrict__ b_ih2, const float* __restrict__ b_hh2,
    const float* __restrict__ fc2_w, const float* __restrict__ fc2_b,
    float* __restrict__ out) {
    const int gt = blockIdx.x * NTHR + threadIdx.x;
    const int GT = NBLK * NTHR;

    // fc1 + relu
    for (int i = gt; i < B * D; i += GT) {
        const int b = i / D, d = i % D;
        float acc = fc1_b[d];
        for (int k = 0; k < D; k++) acc += x[b * D + k] * fc1_w[d * D + k];
        d_hin[i] = fmaxf(acc, 0.f);
    }
    grid_sync();

    // g0 = h_in @ w_ih0^T + b_ih0 (constant over t)
    for (int i = gt; i < B * H3; i += GT) {
        const int b = i / H3, j = i % H3;
        float acc = b_ih0[j];
        for (int k = 0; k < D; k++) acc += d_hin[b * D + k] * w_ih0[j * D + k];
        d_g0[i] = acc;
    }
    grid_sync();

    // layer 0 scan -> ysA  (g constant over t: gstep = 0)
    scan_layer(d_g0, 0, w_hh0, b_hh0, d_ysA);

    // g1 = ysA @ w_ih1^T + b_ih1
    gate_layer(d_ysA, w_ih1, b_ih1, d_gbuf);
    grid_sync();

    // layer 1 scan -> ysB
    scan_layer(d_gbuf, (long)B * H3, w_hh1, b_hh1, d_ysB);

    // g2 = ysB @ w_ih2^T + b_ih2 (reuse gbuf)
    gate_layer(d_ysB, w_ih2, b_ih2, d_gbuf);
    grid_sync();

    // layer 2 scan -> ysA (reused)
    scan_layer(d_gbuf, (long)B * H3, w_hh2, b_hh2, d_ysA);

    // fc2 + permute
    fc2_phase(d_ysA, fc2_w, fc2_b, out);
}

extern "C" void kernel_launch(void* const* d_in, const int* in_sizes, int n_in,
                              void* d_out, int out_size) {
    const float* x     = (const float*)d_in[0];
    const float* fc1_w = (const float*)d_in[1];
    const float* fc1_b = (const float*)d_in[2];
    const float* w_ih0 = (const float*)d_in[3];
    const float* w_hh0 = (const float*)d_in[4];
    const float* b_ih0 = (const float*)d_in[5];
    const float* b_hh0 = (const float*)d_in[6];
    const float* w_ih1 = (const float*)d_in[7];
    const float* w_hh1 = (const float*)d_in[8];
    const float* b_ih1 = (const float*)d_in[9];
    const float* b_hh1 = (const float*)d_in[10];
    const float* w_ih2 = (const float*)d_in[11];
    const float* w_hh2 = (const float*)d_in[12];
    const float* b_ih2 = (const float*)d_in[13];
    const float* b_hh2 = (const float*)d_in[14];
    const float* fc2_w = (const float*)d_in[15];
    const float* fc2_b = (const float*)d_in[16];
    float* out = (float*)d_out;

    cudaFuncSetAttribute(decoder_kernel, cudaFuncAttributeMaxDynamicSharedMemorySize,
                         SMEM_BYTES);
    decoder_kernel<<<NBLK, NTHR, SMEM_BYTES>>>(x, fc1_w, fc1_b,
                                               w_ih0, w_hh0, b_ih0, b_hh0,
                                               w_ih1, w_hh1, b_ih1, b_hh1,
                                               w_ih2, w_hh2, b_ih2, b_hh2,
                                               fc2_w, fc2_b, out);
}

// round 7
// speedup vs baseline: 1.4698x; 1.3964x over previous
#include <cuda_runtime.h>
#include <math.h>

#define D 56
#define H 501
#define T 277
#define O 76
#define B 256
#define H3 1503
#define NBLK 148
#define NSCAN 128          /* blocks that own a scan tile (4 Mt x 32 Nt) */
#define NTHR 512           /* two 256-thread K-halves */
#define KC 32
#define KPAD 512
#define BM 64
#define BN 16              /* per gate */
#define WS_STRIDE 518      /* 518 mod 32 = 6 -> conflict-free across 16 n-threads */
#define HS_STRIDE 34
#define HSOFF (48 * WS_STRIDE)      /* 24864 floats */
#define BUFSZ (BM * HS_STRIDE)      /* 2176 floats */
#define SMEM_BYTES ((HSOFF + 4 * BUFSZ) * 4)   /* 134272 B */

typedef unsigned long long ull;

extern __shared__ float sdyn[];

// ---------------- static device scratch ----------------
__device__ float d_hin[B * D];
__device__ float d_g0[B * H3];
__device__ float d_ysA[T * B * H];
__device__ float d_ysB[T * B * H];
__device__ float d_gbuf[(long)T * B * H3];

// ---------------- grid barrier ----------------
__device__ unsigned int g_arrive = 0;
__device__ volatile unsigned int g_gen = 0;

__device__ __forceinline__ void grid_sync() {
    __syncthreads();
    if (threadIdx.x == 0) {
        __threadfence();
        unsigned int gen = g_gen;
        if (atomicAdd(&g_arrive, 1u) == (unsigned)(NBLK - 1)) {
            g_arrive = 0;
            __threadfence();
            g_gen = gen + 1;
        } else {
            while (g_gen == gen) { }
        }
        __threadfence();
    }
    __syncthreads();
}

// ---------------- packed f32x2 helpers ----------------
__device__ __forceinline__ ull ffma2(ull a, ull b, ull c) {
    ull d;
    asm("fma.rn.f32x2 %0, %1, %2, %3;" : "=l"(d) : "l"(a), "l"(b), "l"(c));
    return d;
}
__device__ __forceinline__ float psum(ull v) {
    unsigned int lo, hi;
    asm("mov.b64 {%0, %1}, %2;" : "=r"(lo), "=r"(hi) : "l"(v));
    return __uint_as_float(lo) + __uint_as_float(hi);
}

// ---------------- persistent 3-gate W tile load (once per layer) ----------------
__device__ void load_W(const float* __restrict__ W, int n0) {
    for (int idx = threadIdx.x; idx < 48 * KPAD; idx += NTHR) {
        const int r = idx >> 9;          // row 0..47 = g*16 + j
        const int k = idx & (KPAD - 1);
        const int g = r >> 4;
        const int n = n0 + (r & 15);
        float v = 0.f;
        if (k < H && n < H) v = W[(g * H + n) * H + k];
        sdyn[r * WS_STRIDE + k] = v;
    }
}

// ---------------- 64x48 tile GEMM vs resident W, split-K across 2 halves ----------------
// out[12] valid only for ks==0 threads (g*4 + i), full-K sums.
__device__ __forceinline__ void tile_compute(const float* __restrict__ src, int m0,
                                             float out[12]) {
    const int tid = threadIdx.x;
    const int ks = tid >> 8;             // K-half: 0 -> k[0,256), 1 -> k[256,512)
    const int ht = tid & 255;
    const int lk = ht & 31;
    const int lm = ht >> 5;              // 0..7
    const int tx = tid & 15;
    const int mrow = ((tid >> 4) & 15) << 2;
    const float* w0p = sdyn + tx * WS_STRIDE;
    const float* w1p = sdyn + (16 + tx) * WS_STRIDE;
    const float* w2p = sdyn + (32 + tx) * WS_STRIDE;
    float* hsb = sdyn + HSOFF + ks * 2 * BUFSZ;

    ull acc[12];
#pragma unroll
    for (int j = 0; j < 12; j++) acc[j] = 0ull;

    float pre[8];
    {
        const int k = ks * 256 + lk;
#pragma unroll
        for (int i = 0; i < 8; i++)
            pre[i] = (k < H) ? src[(long)(m0 + lm + i * 8) * H + k] : 0.f;
#pragma unroll
        for (int i = 0; i < 8; i++) hsb[(lm + i * 8) * HS_STRIDE + lk] = pre[i];
    }
    __syncthreads();

#pragma unroll 1
    for (int c = 0; c < 8; c++) {
        if (c < 7) {
            const int k = ks * 256 + (c + 1) * KC + lk;
#pragma unroll
            for (int i = 0; i < 8; i++)
                pre[i] = (k < H) ? src[(long)(m0 + lm + i * 8) * H + k] : 0.f;
        }
        const float* buf = hsb + (c & 1) * BUFSZ + mrow * HS_STRIDE;
        const int cb = ks * 256 + c * KC;
#pragma unroll
        for (int p = 0; p < 16; p++) {
            const ull hp0 = *(const ull*)(buf + 0 * HS_STRIDE + 2 * p);
            const ull hp1 = *(const ull*)(buf + 1 * HS_STRIDE + 2 * p);
            const ull hp2 = *(const ull*)(buf + 2 * HS_STRIDE + 2 * p);
            const ull hp3 = *(const ull*)(buf + 3 * HS_STRIDE + 2 * p);
            const ull w0 = *(const ull*)(w0p + cb + 2 * p);
            const ull w1 = *(const ull*)(w1p + cb + 2 * p);
            const ull w2 = *(const ull*)(w2p + cb + 2 * p);
            acc[0]  = ffma2(hp0, w0, acc[0]);
            acc[1]  = ffma2(hp1, w0, acc[1]);
            acc[2]  = ffma2(hp2, w0, acc[2]);
            acc[3]  = ffma2(hp3, w0, acc[3]);
            acc[4]  = ffma2(hp0, w1, acc[4]);
            acc[5]  = ffma2(hp1, w1, acc[5]);
            acc[6]  = ffma2(hp2, w1, acc[6]);
            acc[7]  = ffma2(hp3, w1, acc[7]);
            acc[8]  = ffma2(hp0, w2, acc[8]);
            acc[9]  = ffma2(hp1, w2, acc[9]);
            acc[10] = ffma2(hp2, w2, acc[10]);
            acc[11] = ffma2(hp3, w2, acc[11]);
        }
        if (c < 7) {
            float* nb = hsb + ((c + 1) & 1) * BUFSZ;
#pragma unroll
            for (int i = 0; i < 8; i++) nb[(lm + i * 8) * HS_STRIDE + lk] = pre[i];
            __syncthreads();
        }
    }

    // cross-half reduction through smem (reuse h-staging area)
    __syncthreads();
    float* red = sdyn + HSOFF;
    if (ks == 1) {
#pragma unroll
        for (int j = 0; j < 12; j++) red[ht * 12 + j] = psum(acc[j]);
    }
    __syncthreads();
    if (ks == 0) {
#pragma unroll
        for (int j = 0; j < 12; j++) out[j] = psum(acc[j]) + red[ht * 12 + j];
    }
    __syncthreads();   // protect red area before next tile's staging
}

// ---------------- scan of one GRU layer (W resident across all timesteps) ----------------
__device__ void scan_layer(const float* __restrict__ gsrc, long gstep,
                           const float* __restrict__ Whh,
                           const float* __restrict__ bhh,
                           float* __restrict__ ybuf) {
    const bool active = blockIdx.x < NSCAN;
    const int mt = blockIdx.x >> 5;
    const int nt = blockIdx.x & 31;
    const int m0 = mt * BM;
    const int n0 = nt * BN;
    const int tid = threadIdx.x;
    const int ks = tid >> 8;
    const int tx = tid & 15;
    const int mrow = ((tid >> 4) & 15) << 2;
    const int n = n0 + tx;

    if (active) load_W(Whh, n0);
    __syncthreads();

    float br = 0.f, bz = 0.f, bnn = 0.f;
    if (active && n < H) { br = bhh[n]; bz = bhh[H + n]; bnn = bhh[2 * H + n]; }

    for (int t = 0; t < T; t++) {
        if (active) {
            const float* hprev = t ? ybuf + (long)(t - 1) * B * H : nullptr;

            // hoist epilogue global loads ahead of the K loop
            float ga[4], gb[4], gc[4], hp[4];
            if (ks == 0 && n < H) {
                const float* gt = gsrc + (long)t * gstep;
#pragma unroll
                for (int i = 0; i < 4; i++) {
                    const int m = m0 + mrow + i;
                    const float* gr = gt + (long)m * H3;
                    ga[i] = gr[n];
                    gb[i] = gr[H + n];
                    gc[i] = gr[2 * H + n];
                    hp[i] = hprev ? hprev[(long)m * H + n] : 0.f;
                }
            }

            float out[12];
#pragma unroll
            for (int j = 0; j < 12; j++) out[j] = 0.f;
            if (hprev) tile_compute(hprev, m0, out);

            if (ks == 0 && n < H) {
#pragma unroll
                for (int i = 0; i < 4; i++) {
                    const int m = m0 + mrow + i;
                    const float r = 1.f / (1.f + __expf(-(ga[i] + out[i] + br)));
                    const float z = 1.f / (1.f + __expf(-(gb[i] + out[4 + i] + bz)));
                    const float nn = tanhf(gc[i] + r * (out[8 + i] + bnn));
                    ybuf[(long)t * B * H + (long)m * H + n] = (1.f - z) * nn + z * hp[i];
                }
            }
        }
        grid_sync();
    }
}

// ---------------- batched input-gate GEMM (W resident across all M tiles) ----------------
__device__ void gate_layer(const float* __restrict__ Y,
                           const float* __restrict__ Wih,
                           const float* __restrict__ bih,
                           float* __restrict__ G) {
    const int nt = blockIdx.x & 31;
    const int mt0 = blockIdx.x >> 5;                 // 0..4
    const int stride = (nt < (NBLK - NSCAN)) ? 5 : 4;
    const int n0 = nt * BN;
    const int tid = threadIdx.x;
    const int ks = tid >> 8;
    const int tx = tid & 15;
    const int mrow = ((tid >> 4) & 15) << 2;
    const int n = n0 + tx;
    const int MT = (T * B) / BM;   // 1108

    load_W(Wih, n0);
    __syncthreads();

    float bb0 = 0.f, bb1 = 0.f, bb2 = 0.f;
    if (n < H) { bb0 = bih[n]; bb1 = bih[H + n]; bb2 = bih[2 * H + n]; }

    for (int mt = mt0; mt < MT; mt += stride) {
        const int m0 = mt * BM;
        float out[12];
#pragma unroll
        for (int j = 0; j < 12; j++) out[j] = 0.f;
        tile_compute(Y, m0, out);

        if (ks == 0 && n < H) {
#pragma unroll
            for (int i = 0; i < 4; i++) {
                const long m = m0 + mrow + i;
                G[m * H3 + n]         = out[i] + bb0;
                G[m * H3 + H + n]     = out[4 + i] + bb1;
                G[m * H3 + 2 * H + n] = out[8 + i] + bb2;
            }
        }
    }
}

// ---------------- fc2 + permute to (B, O, T) ----------------
__device__ void fc2_phase(const float* __restrict__ Y,
                          const float* __restrict__ W,
                          const float* __restrict__ bias,
                          float* __restrict__ out) {
    const int wid = threadIdx.x >> 5;   // 0..15
    const int lane = threadIdx.x & 31;
    const int M = T * B;
    float* rows = sdyn;                 // 16 rows of 502 floats
    for (int base = blockIdx.x * 16; base < M; base += NBLK * 16) {
        const int row = base + wid;
        if (row < M) {
            for (int k = lane; k < H; k += 32) rows[wid * 502 + k] = Y[(long)row * H + k];
            __syncwarp();
            const int t = row / B;
            const int b = row % B;
            for (int o = lane; o < O; o += 32) {
                float acc = bias[o];
                const float* w = W + o * H;
                for (int k = 0; k < H; k++) acc += rows[wid * 502 + k] * w[k];
                out[((long)b * O + o) * T + t] = acc;
            }
            __syncwarp();
        }
    }
}

// ---------------- persistent mega-kernel ----------------
__global__ void __launch_bounds__(NTHR, 1) decoder_kernel(
    const float* __restrict__ x,
    const float* __restrict__ fc1_w, const float* __restrict__ fc1_b,
    const float* __restrict__ w_ih0, const float* __restrict__ w_hh0,
    const float* __restrict__ b_ih0, const float* __restrict__ b_hh0,
    const float* __restrict__ w_ih1, const float* __restrict__ w_hh1,
    const float* __restrict__ b_ih1, const float* __restrict__ b_hh1,
    const float* __restrict__ w_ih2, const float* __restrict__ w_hh2,
    const float* __restrict__ b_ih2, const float* __restrict__ b_hh2,
    const float* __restrict__ fc2_w, const float* __restrict__ fc2_b,
    float* __restrict__ out) {
    const int gt = blockIdx.x * NTHR + threadIdx.x;
    const int GT = NBLK * NTHR;

    // fc1 + relu
    for (int i = gt; i < B * D; i += GT) {
        const int b = i / D, d = i % D;
        float acc = fc1_b[d];
        for (int k = 0; k < D; k++) acc += x[b * D + k] * fc1_w[d * D + k];
        d_hin[i] = fmaxf(acc, 0.f);
    }
    grid_sync();

    // g0 = h_in @ w_ih0^T + b_ih0 (constant over t)
    for (int i = gt; i < B * H3; i += GT) {
        const int b = i / H3, j = i % H3;
        float acc = b_ih0[j];
        for (int k = 0; k < D; k++) acc += d_hin[b * D + k] * w_ih0[j * D + k];
        d_g0[i] = acc;
    }
    grid_sync();

    // layer 0 scan -> ysA (g constant over t: gstep = 0)
    scan_layer(d_g0, 0, w_hh0, b_hh0, d_ysA);

    // g1 = ysA @ w_ih1^T + b_ih1
    gate_layer(d_ysA, w_ih1, b_ih1, d_gbuf);
    grid_sync();

    // layer 1 scan -> ysB
    scan_layer(d_gbuf, (long)B * H3, w_hh1, b_hh1, d_ysB);

    // g2 = ysB @ w_ih2^T + b_ih2 (reuse gbuf)
    gate_layer(d_ysB, w_ih2, b_ih2, d_gbuf);
    grid_sync();

    // layer 2 scan -> ysA (reused)
    scan_layer(d_gbuf, (long)B * H3, w_hh2, b_hh2, d_ysA);

    // fc2 + permute
    fc2_phase(d_ysA, fc2_w, fc2_b, out);
}

extern "C" void kernel_launch(void* const* d_in, const int* in_sizes, int n_in,
                              void* d_out, int out_size) {
    const float* x     = (const float*)d_in[0];
    const float* fc1_w = (const float*)d_in[1];
    const float* fc1_b = (const float*)d_in[2];
    const float* w_ih0 = (const float*)d_in[3];
    const float* w_hh0 = (const float*)d_in[4];
    const float* b_ih0 = (const float*)d_in[5];
    const float* b_hh0 = (const float*)d_in[6];
    const float* w_ih1 = (const float*)d_in[7];
    const float* w_hh1 = (const float*)d_in[8];
    const float* b_ih1 = (const float*)d_in[9];
    const float* b_hh1 = (const float*)d_in[10];
    const float* w_ih2 = (const float*)d_in[11];
    const float* w_hh2 = (const float*)d_in[12];
    const float* b_ih2 = (const float*)d_in[13];
    const float* b_hh2 = (const float*)d_in[14];
    const float* fc2_w = (const float*)d_in[15];
    const float* fc2_b = (const float*)d_in[16];
    float* out = (float*)d_out;

    cudaFuncSetAttribute(decoder_kernel, cudaFuncAttributeMaxDynamicSharedMemorySize,
                         SMEM_BYTES);
    decoder_kernel<<<NBLK, NTHR, SMEM_BYTES>>>(x, fc1_w, fc1_b,
                                               w_ih0, w_hh0, b_ih0, b_hh0,
                                               w_ih1, w_hh1, b_ih1, b_hh1,
                                               w_ih2, w_hh2, b_ih2, b_hh2,
                                               fc2_w, fc2_b, out);
}

// round 8
// speedup vs baseline: 1.5016x; 1.0217x over previous
#include <cuda_runtime.h>
#include <math.h>

#define D 56
#define H 501
#define T 277
#define O 76
#define B 256
#define H3 1503
#define NBLK 148
#define NSCAN 128          /* blocks that own a scan tile (4 Mt x 32 Nt) */
#define NTHR 512           /* two 256-thread K-halves */
#define KC 32
#define KPAD 512
#define BM 64
#define BN 16              /* per gate */
#define WS_STRIDE 518      /* 518 mod 32 = 6 -> conflict-free across 16 n-threads */
#define HS_STRIDE 34
#define HSOFF (48 * WS_STRIDE)      /* 24864 floats */
#define BUFSZ (BM * HS_STRIDE)      /* 2176 floats */
#define SMEM_BYTES ((HSOFF + 4 * BUFSZ) * 4)   /* 134272 B */

typedef unsigned long long ull;

extern __shared__ float sdyn[];

// ---------------- static device scratch ----------------
__device__ float d_hin[B * D];
__device__ float d_g0[B * H3];
__device__ float d_ysA[T * B * H];
__device__ float d_ysB[T * B * H];
__device__ float d_gbuf[(long)T * B * H3];

// ---------------- grid barrier ----------------
__device__ unsigned int g_arrive = 0;
__device__ volatile unsigned int g_gen = 0;

__device__ __forceinline__ void grid_sync() {
    __syncthreads();
    if (threadIdx.x == 0) {
        __threadfence();
        unsigned int gen = g_gen;
        if (atomicAdd(&g_arrive, 1u) == (unsigned)(NBLK - 1)) {
            g_arrive = 0;
            __threadfence();
            g_gen = gen + 1;
        } else {
            while (g_gen == gen) { }
        }
        __threadfence();
    }
    __syncthreads();
}

// ---------------- packed f32x2 helpers ----------------
__device__ __forceinline__ ull ffma2(ull a, ull b, ull c) {
    ull d;
    asm("fma.rn.f32x2 %0, %1, %2, %3;" : "=l"(d) : "l"(a), "l"(b), "l"(c));
    return d;
}
__device__ __forceinline__ float psum(ull v) {
    unsigned int lo, hi;
    asm("mov.b64 {%0, %1}, %2;" : "=r"(lo), "=r"(hi) : "l"(v));
    return __uint_as_float(lo) + __uint_as_float(hi);
}

// ---------------- persistent 3-gate W tile load (once per layer) ----------------
__device__ void load_W(const float* __restrict__ W, int n0) {
    for (int idx = threadIdx.x; idx < 48 * KPAD; idx += NTHR) {
        const int r = idx >> 9;          // row 0..47 = g*16 + j
        const int k = idx & (KPAD - 1);
        const int g = r >> 4;
        const int n = n0 + (r & 15);
        float v = 0.f;
        if (k < H && n < H) v = W[(g * H + n) * H + k];
        sdyn[r * WS_STRIDE + k] = v;
    }
}

// ---------------- 64x48 tile GEMM vs resident W, split-K across 2 halves ----------------
// out[12] valid only for ks==0 threads (g*4 + i), full-K sums.
__device__ __forceinline__ void tile_compute(const float* __restrict__ src, int m0,
                                             float out[12]) {
    const int tid = threadIdx.x;
    const int ks = tid >> 8;             // K-half: 0 -> k[0,256), 1 -> k[256,512)
    const int ht = tid & 255;
    const int lk = ht & 31;
    const int lm = ht >> 5;              // 0..7
    const int tx = tid & 15;
    const int mrow = ((tid >> 4) & 15) << 2;
    const float* w0p = sdyn + tx * WS_STRIDE;
    const float* w1p = sdyn + (16 + tx) * WS_STRIDE;
    const float* w2p = sdyn + (32 + tx) * WS_STRIDE;
    float* hsb = sdyn + HSOFF + ks * 2 * BUFSZ;

    ull acc[12];
#pragma unroll
    for (int j = 0; j < 12; j++) acc[j] = 0ull;

    float pre[8];
    {
        const int k = ks * 256 + lk;
#pragma unroll
        for (int i = 0; i < 8; i++)
            pre[i] = (k < H) ? src[(long)(m0 + lm + i * 8) * H + k] : 0.f;
#pragma unroll
        for (int i = 0; i < 8; i++) hsb[(lm + i * 8) * HS_STRIDE + lk] = pre[i];
    }
    __syncthreads();

#pragma unroll 1
    for (int c = 0; c < 8; c++) {
        if (c < 7) {
            const int k = ks * 256 + (c + 1) * KC + lk;
#pragma unroll
            for (int i = 0; i < 8; i++)
                pre[i] = (k < H) ? src[(long)(m0 + lm + i * 8) * H + k] : 0.f;
        }
        const float* buf = hsb + (c & 1) * BUFSZ + mrow * HS_STRIDE;
        const int cb = ks * 256 + c * KC;
#pragma unroll
        for (int p = 0; p < 16; p++) {
            const ull hp0 = *(const ull*)(buf + 0 * HS_STRIDE + 2 * p);
            const ull hp1 = *(const ull*)(buf + 1 * HS_STRIDE + 2 * p);
            const ull hp2 = *(const ull*)(buf + 2 * HS_STRIDE + 2 * p);
            const ull hp3 = *(const ull*)(buf + 3 * HS_STRIDE + 2 * p);
            const ull w0 = *(const ull*)(w0p + cb + 2 * p);
            const ull w1 = *(const ull*)(w1p + cb + 2 * p);
            const ull w2 = *(const ull*)(w2p + cb + 2 * p);
            acc[0]  = ffma2(hp0, w0, acc[0]);
            acc[1]  = ffma2(hp1, w0, acc[1]);
            acc[2]  = ffma2(hp2, w0, acc[2]);
            acc[3]  = ffma2(hp3, w0, acc[3]);
            acc[4]  = ffma2(hp0, w1, acc[4]);
            acc[5]  = ffma2(hp1, w1, acc[5]);
            acc[6]  = ffma2(hp2, w1, acc[6]);
            acc[7]  = ffma2(hp3, w1, acc[7]);
            acc[8]  = ffma2(hp0, w2, acc[8]);
            acc[9]  = ffma2(hp1, w2, acc[9]);
            acc[10] = ffma2(hp2, w2, acc[10]);
            acc[11] = ffma2(hp3, w2, acc[11]);
        }
        if (c < 7) {
            float* nb = hsb + ((c + 1) & 1) * BUFSZ;
#pragma unroll
            for (int i = 0; i < 8; i++) nb[(lm + i * 8) * HS_STRIDE + lk] = pre[i];
            __syncthreads();
        }
    }

    // cross-half reduction through smem (reuse h-staging area)
    __syncthreads();
    float* red = sdyn + HSOFF;
    if (ks == 1) {
#pragma unroll
        for (int j = 0; j < 12; j++) red[ht * 12 + j] = psum(acc[j]);
    }
    __syncthreads();
    if (ks == 0) {
#pragma unroll
        for (int j = 0; j < 12; j++) out[j] = psum(acc[j]) + red[ht * 12 + j];
    }
    __syncthreads();   // protect red area before next tile's staging
}

// ---------------- scan of one GRU layer (W resident across all timesteps) ----------------
__device__ void scan_layer(const float* __restrict__ gsrc, long gstep,
                           const float* __restrict__ Whh,
                           const float* __restrict__ bhh,
                           float* __restrict__ ybuf) {
    const bool active = blockIdx.x < NSCAN;
    const int mt = blockIdx.x >> 5;
    const int nt = blockIdx.x & 31;
    const int m0 = mt * BM;
    const int n0 = nt * BN;
    const int tid = threadIdx.x;
    const int ks = tid >> 8;
    const int tx = tid & 15;
    const int mrow = ((tid >> 4) & 15) << 2;
    const int n = n0 + tx;

    if (active) load_W(Whh, n0);
    __syncthreads();

    float br = 0.f, bz = 0.f, bnn = 0.f;
    if (active && n < H) { br = bhh[n]; bz = bhh[H + n]; bnn = bhh[2 * H + n]; }

    for (int t = 0; t < T; t++) {
        if (active) {
            const float* hprev = t ? ybuf + (long)(t - 1) * B * H : nullptr;

            // hoist epilogue global loads ahead of the K loop
            float ga[4], gb[4], gc[4], hp[4];
            if (ks == 0 && n < H) {
                const float* gt = gsrc + (long)t * gstep;
#pragma unroll
                for (int i = 0; i < 4; i++) {
                    const int m = m0 + mrow + i;
                    const float* gr = gt + (long)m * H3;
                    ga[i] = gr[n];
                    gb[i] = gr[H + n];
                    gc[i] = gr[2 * H + n];
                    hp[i] = hprev ? hprev[(long)m * H + n] : 0.f;
                }
            }

            float out[12];
#pragma unroll
            for (int j = 0; j < 12; j++) out[j] = 0.f;
            if (hprev) tile_compute(hprev, m0, out);

            if (ks == 0 && n < H) {
#pragma unroll
                for (int i = 0; i < 4; i++) {
                    const int m = m0 + mrow + i;
                    const float r = 1.f / (1.f + __expf(-(ga[i] + out[i] + br)));
                    const float z = 1.f / (1.f + __expf(-(gb[i] + out[4 + i] + bz)));
                    const float nn = tanhf(gc[i] + r * (out[8 + i] + bnn));
                    ybuf[(long)t * B * H + (long)m * H + n] = (1.f - z) * nn + z * hp[i];
                }
            }
        }
        grid_sync();
    }
}

// ---------------- batched input-gate GEMM (W resident across all M tiles) ----------------
__device__ void gate_layer(const float* __restrict__ Y,
                           const float* __restrict__ Wih,
                           const float* __restrict__ bih,
                           float* __restrict__ G) {
    const int nt = blockIdx.x & 31;
    const int mt0 = blockIdx.x >> 5;                 // 0..4
    const int stride = (nt < (NBLK - NSCAN)) ? 5 : 4;
    const int n0 = nt * BN;
    const int tid = threadIdx.x;
    const int ks = tid >> 8;
    const int tx = tid & 15;
    const int mrow = ((tid >> 4) & 15) << 2;
    const int n = n0 + tx;
    const int MT = (T * B) / BM;   // 1108

    load_W(Wih, n0);
    __syncthreads();

    float bb0 = 0.f, bb1 = 0.f, bb2 = 0.f;
    if (n < H) { bb0 = bih[n]; bb1 = bih[H + n]; bb2 = bih[2 * H + n]; }

    for (int mt = mt0; mt < MT; mt += stride) {
        const int m0 = mt * BM;
        float out[12];
#pragma unroll
        for (int j = 0; j < 12; j++) out[j] = 0.f;
        tile_compute(Y, m0, out);

        if (ks == 0 && n < H) {
#pragma unroll
            for (int i = 0; i < 4; i++) {
                const long m = m0 + mrow + i;
                G[m * H3 + n]         = out[i] + bb0;
                G[m * H3 + H + n]     = out[4 + i] + bb1;
                G[m * H3 + 2 * H + n] = out[8 + i] + bb2;
            }
        }
    }
}

// ---------------- fc2 + permute to (B, O, T) ----------------
__device__ void fc2_phase(const float* __restrict__ Y,
                          const float* __restrict__ W,
                          const float* __restrict__ bias,
                          float* __restrict__ out) {
    const int wid = threadIdx.x >> 5;   // 0..15
    const int lane = threadIdx.x & 31;
    const int M = T * B;
    float* rows = sdyn;                 // 16 rows of 502 floats
    for (int base = blockIdx.x * 16; base < M; base += NBLK * 16) {
        const int row = base + wid;
        if (row < M) {
            for (int k = lane; k < H; k += 32) rows[wid * 502 + k] = Y[(long)row * H + k];
            __syncwarp();
            const int t = row / B;
            const int b = row % B;
            for (int o = lane; o < O; o += 32) {
                float acc = bias[o];
                const float* w = W + o * H;
                for (int k = 0; k < H; k++) acc += rows[wid * 502 + k] * w[k];
                out[((long)b * O + o) * T + t] = acc;
            }
            __syncwarp();
        }
    }
}

// ---------------- persistent mega-kernel ----------------
__global__ void __launch_bounds__(NTHR, 1) decoder_kernel(
    const float* __restrict__ x,
    const float* __restrict__ fc1_w, const float* __restrict__ fc1_b,
    const float* __restrict__ w_ih0, const float* __restrict__ w_hh0,
    const float* __restrict__ b_ih0, const float* __restrict__ b_hh0,
    const float* __restrict__ w_ih1, const float* __restrict__ w_hh1,
    const float* __restrict__ b_ih1, const float* __restrict__ b_hh1,
    const float* __restrict__ w_ih2, const float* __restrict__ w_hh2,
    const float* __restrict__ b_ih2, const float* __restrict__ b_hh2,
    const float* __restrict__ fc2_w, const float* __restrict__ fc2_b,
    float* __restrict__ out) {
    const int gt = blockIdx.x * NTHR + threadIdx.x;
    const int GT = NBLK * NTHR;

    // fc1 + relu
    for (int i = gt; i < B * D; i += GT) {
        const int b = i / D, d = i % D;
        float acc = fc1_b[d];
        for (int k = 0; k < D; k++) acc += x[b * D + k] * fc1_w[d * D + k];
        d_hin[i] = fmaxf(acc, 0.f);
    }
    grid_sync();

    // g0 = h_in @ w_ih0^T + b_ih0 (constant over t)
    for (int i = gt; i < B * H3; i += GT) {
        const int b = i / H3, j = i % H3;
        float acc = b_ih0[j];
        for (int k = 0; k < D; k++) acc += d_hin[b * D + k] * w_ih0[j * D + k];
        d_g0[i] = acc;
    }
    grid_sync();

    // layer 0 scan -> ysA (g constant over t: gstep = 0)
    scan_layer(d_g0, 0, w_hh0, b_hh0, d_ysA);

    // g1 = ysA @ w_ih1^T + b_ih1
    gate_layer(d_ysA, w_ih1, b_ih1, d_gbuf);
    grid_sync();

    // layer 1 scan -> ysB
    scan_layer(d_gbuf, (long)B * H3, w_hh1, b_hh1, d_ysB);

    // g2 = ysB @ w_ih2^T + b_ih2 (reuse gbuf)
    gate_layer(d_ysB, w_ih2, b_ih2, d_gbuf);
    grid_sync();

    // layer 2 scan -> ysA (reused)
    scan_layer(d_gbuf, (long)B * H3, w_hh2, b_hh2, d_ysA);

    // fc2 + permute
    fc2_phase(d_ysA, fc2_w, fc2_b, out);
}

extern "C" void kernel_launch(void* const* d_in, const int* in_sizes, int n_in,
                              void* d_out, int out_size) {
    const float* x     = (const float*)d_in[0];
    const float* fc1_w = (const float*)d_in[1];
    const float* fc1_b = (const float*)d_in[2];
    const float* w_ih0 = (const float*)d_in[3];
    const float* w_hh0 = (const float*)d_in[4];
    const float* b_ih0 = (const float*)d_in[5];
    const float* b_hh0 = (const float*)d_in[6];
    const float* w_ih1 = (const float*)d_in[7];
    const float* w_hh1 = (const float*)d_in[8];
    const float* b_ih1 = (const float*)d_in[9];
    const float* b_hh1 = (const float*)d_in[10];
    const float* w_ih2 = (const float*)d_in[11];
    const float* w_hh2 = (const float*)d_in[12];
    const float* b_ih2 = (const float*)d_in[13];
    const float* b_hh2 = (const float*)d_in[14];
    const float* fc2_w = (const float*)d_in[15];
    const float* fc2_b = (const float*)d_in[16];
    float* out = (float*)d_out;

    cudaFuncSetAttribute(decoder_kernel, cudaFuncAttributeMaxDynamicSharedMemorySize,
                         SMEM_BYTES);
    decoder_kernel<<<NBLK, NTHR, SMEM_BYTES>>>(x, fc1_w, fc1_b,
                                               w_ih0, w_hh0, b_ih0, b_hh0,
                                               w_ih1, w_hh1, b_ih1, b_hh1,
                                               w_ih2, w_hh2, b_ih2, b_hh2,
                                               fc2_w, fc2_b, out);
}

// round 12
// speedup vs baseline: 2.8377x; 1.8898x over previous
#include <cuda_runtime.h>
#include <cuda_bf16.h>
#include <math.h>
#include <stdint.h>

#define D 56
#define H 501
#define T 277
#define O 76
#define B 256
#define H3 1503
#define NBLK 128
#define NTHR 256
#define KPAD 512
#define MT_GATE 1108

typedef unsigned long long ull;
typedef uint32_t u32;
typedef __nv_bfloat16 bf16;

// ---- smem layout (bytes) ----
#define WSTRB 1040
#define WHI_OFF 0
#define WLO_OFF 49920
#define ASTRB 272
#define ABUF_OFF 99840
#define ABUF_STRIDE 34816
#define SMEM_BYTES (ABUF_OFF + 2 * ABUF_STRIDE)   /* 169472 */

extern __shared__ char smc[];

// ---- static device scratch ----
__device__ float d_hin[B * D];
__device__ float d_g0[B * H3];
__device__ float d_gbuf[(long)T * B * H3];
__device__ bf16 d_yAhi[(long)T * B * KPAD], d_yAlo[(long)T * B * KPAD];
__device__ bf16 d_yBhi[(long)T * B * KPAD], d_yBlo[(long)T * B * KPAD];
__device__ bf16 d_whh[3][2][H3 * KPAD];
__device__ bf16 d_wih[2][2][H3 * KPAD];

// ---- grid barrier ----
__device__ unsigned int g_arrive = 0;
__device__ volatile unsigned int g_gen = 0;
__device__ __forceinline__ void grid_sync() {
    __syncthreads();
    if (threadIdx.x == 0) {
        __threadfence();
        unsigned int gen = g_gen;
        if (atomicAdd(&g_arrive, 1u) == (unsigned)(NBLK - 1)) {
            g_arrive = 0;
            __threadfence();
            g_gen = gen + 1;
        } else {
            while (g_gen == gen) { }
        }
        __threadfence();
    }
    __syncthreads();
}

// ---- PTX helpers ----
__device__ __forceinline__ u32 s2u(const void* p) {
    u32 a;
    asm("{ .reg .u64 t; cvta.to.shared.u64 t, %1; cvt.u32.u64 %0, t; }" : "=r"(a) : "l"(p));
    return a;
}
#define LDSM_X4(r0, r1, r2, r3, a) \
    asm volatile("ldmatrix.sync.aligned.m8n8.x4.shared.b16 {%0,%1,%2,%3}, [%4];" \
                 : "=r"(r0), "=r"(r1), "=r"(r2), "=r"(r3) : "r"(a))
#define LDSM_X2(r0, r1, a) \
    asm volatile("ldmatrix.sync.aligned.m8n8.x2.shared.b16 {%0,%1}, [%2];" \
                 : "=r"(r0), "=r"(r1) : "r"(a))
#define CP_ASYNC(sdst, gsrc) \
    asm volatile("cp.async.cg.shared.global [%0], [%1], 16;" :: "r"(sdst), "l"(gsrc))
#define CP_COMMIT() asm volatile("cp.async.commit_group;" ::: "memory")
#define CP_WAIT1() asm volatile("cp.async.wait_group 1;" ::: "memory")
#define CP_WAIT0() asm volatile("cp.async.wait_group 0;" ::: "memory")

__device__ __forceinline__ void hmma(float c[4], const u32 a[4], u32 b0, u32 b1) {
    asm volatile(
        "mma.sync.aligned.m16n8k16.row.col.f32.bf16.bf16.f32 "
        "{%0,%1,%2,%3}, {%4,%5,%6,%7}, {%8,%9}, {%0,%1,%2,%3};"
        : "+f"(c[0]), "+f"(c[1]), "+f"(c[2]), "+f"(c[3])
        : "r"(a[0]), "r"(a[1]), "r"(a[2]), "r"(a[3]), "r"(b0), "r"(b1));
}

__device__ __forceinline__ float sigm(float x) { return 1.f / (1.f + __expf(-x)); }

// ---- weight hi/lo split precompute (k padded to KPAD with zeros) ----
__device__ void split_mat(const float* __restrict__ w, bf16* __restrict__ hi,
                          bf16* __restrict__ lo) {
    const long n = (long)H3 * KPAD;
    for (long i = (long)blockIdx.x * NTHR + threadIdx.x; i < n; i += (long)NBLK * NTHR) {
        const int r = (int)(i >> 9);
        const int k = (int)(i & (KPAD - 1));
        const float v = (k < H) ? w[(long)r * H + k] : 0.f;
        const bf16 h = __float2bfloat16(v);
        hi[i] = h;
        lo[i] = __float2bfloat16(v - __bfloat162float(h));
    }
}

// ---- load W hi+lo tile into smem: rows r = g*16 + (n - n0), k 0..511 ----
__device__ void load_W(const bf16* __restrict__ whi, const bf16* __restrict__ wlo, int n0) {
    for (int idx = threadIdx.x; idx < 3072; idx += NTHR) {
        const int r = idx >> 6;
        const int seg = idx & 63;
        const int g = r >> 4;
        const int n = n0 + (r & 15);
        uint4 vh = make_uint4(0, 0, 0, 0), vl = vh;
        if (n < H) {
            const long off = (long)(g * H + n) * KPAD + seg * 8;
            vh = *(const uint4*)(whi + off);
            vl = *(const uint4*)(wlo + off);
        }
        const u32 so = (u32)r * WSTRB + seg * 16;
        *(uint4*)(smc + WHI_OFF + so) = vh;
        *(uint4*)(smc + WLO_OFF + so) = vl;
    }
}

// ---- stage one 64x128 A chunk (hi+lo) via cp.async ----
__device__ __forceinline__ void stage_chunk(const bf16* __restrict__ ahi,
                                            const bf16* __restrict__ alo,
                                            int m0, int c, u32 sA) {
    const int tid = threadIdx.x;
#pragma unroll
    for (int i = 0; i < 4; i++) {
        const int idx = tid + i * NTHR;
        const int row = idx >> 4;
        const int seg = idx & 15;
        const long go = (long)(m0 + row) * KPAD + c * 128 + seg * 8;
        const u32 so = (u32)row * ASTRB + seg * 16;
        CP_ASYNC(sA + so, ahi + go);
        CP_ASYNC(sA + 17408 + so, alo + go);
    }
}

// ---- one 64x48x512 tile with 3-term bf16 compensation ----
// ahi/alo are LAYER BASE pointers; m0 selects the 64-row window.
__device__ void run_tile(const bf16* __restrict__ ahi, const bf16* __restrict__ alo,
                         int m0, u32 sb, float cf[3][4]) {
    const int tid = threadIdx.x;
    const int w = tid >> 5;
    const int mi = w >> 1;
    const int ns = w & 1;
    const int lane = tid & 31;

#pragma unroll
    for (int g = 0; g < 3; g++)
#pragma unroll
        for (int j = 0; j < 4; j++) cf[g][j] = 0.f;

    const u32 aoff = (u32)(mi * 16 + (lane & 15)) * ASTRB + (lane >> 4) * 16;
    const int gsel = lane >> 4;
    const int khalf = (lane >> 3) & 1;
    const u32 b01off = (u32)(gsel * 16 + ns * 8 + (lane & 7)) * WSTRB + khalf * 16;
    const int l2 = lane & 15;
    const u32 b2off = (u32)(32 + ns * 8 + (l2 & 7)) * WSTRB + (l2 >> 3) * 16;

    stage_chunk(ahi, alo, m0, 0, sb + ABUF_OFF);
    CP_COMMIT();

#pragma unroll 1
    for (int c = 0; c < 4; c++) {
        if (c < 3) {
            stage_chunk(ahi, alo, m0, c + 1, sb + ABUF_OFF + ((c + 1) & 1) * ABUF_STRIDE);
            CP_COMMIT();
            CP_WAIT1();
        } else {
            CP_WAIT0();
        }
        __syncthreads();

        const u32 aH = sb + ABUF_OFF + (c & 1) * ABUF_STRIDE + aoff;
        const u32 aL = aH + 17408;
        const u32 bH01 = sb + WHI_OFF + b01off + c * 256;
        const u32 bH2 = sb + WHI_OFF + b2off + c * 256;
        const u32 bL01 = sb + WLO_OFF + b01off + c * 256;
        const u32 bL2 = sb + WLO_OFF + b2off + c * 256;

#pragma unroll
        for (int kk = 0; kk < 8; kk++) {
            const u32 ko = kk * 32;
            u32 ah[4], al[4], bh[4], bh2[2], bl[4], bl2[2];
            LDSM_X4(ah[0], ah[1], ah[2], ah[3], aH + ko);
            LDSM_X4(al[0], al[1], al[2], al[3], aL + ko);
            LDSM_X4(bh[0], bh[1], bh[2], bh[3], bH01 + ko);
            LDSM_X2(bh2[0], bh2[1], bH2 + ko);
            LDSM_X4(bl[0], bl[1], bl[2], bl[3], bL01 + ko);
            LDSM_X2(bl2[0], bl2[1], bL2 + ko);
            hmma(cf[0], ah, bh[0], bh[1]);
            hmma(cf[1], ah, bh[2], bh[3]);
            hmma(cf[2], ah, bh2[0], bh2[1]);
            hmma(cf[0], al, bh[0], bh[1]);
            hmma(cf[1], al, bh[2], bh[3]);
            hmma(cf[2], al, bh2[0], bh2[1]);
            hmma(cf[0], ah, bl[0], bl[1]);
            hmma(cf[1], ah, bl[2], bl[3]);
            hmma(cf[2], ah, bl2[0], bl2[1]);
        }
        __syncthreads();
    }
}

// ---- GRU layer scan: h carried in registers per thread ----
__device__ void scan_layer(const float* __restrict__ gsrc, long gstep,
                           const bf16* __restrict__ whi, const bf16* __restrict__ wlo,
                           const float* __restrict__ bhh,
                           bf16* __restrict__ yhi, bf16* __restrict__ ylo, u32 sb) {
    const int m0 = (blockIdx.x >> 5) * 64;
    const int n0 = (blockIdx.x & 31) * 16;
    const int tid = threadIdx.x;
    const int w = tid >> 5;
    const int mi = w >> 1;
    const int ns = w & 1;
    const int lane = tid & 31;
    const int grp = lane >> 2;
    const int tig = lane & 3;

    load_W(whi, wlo, n0);
    __syncthreads();

    const int rows[2] = {m0 + mi * 16 + grp, m0 + mi * 16 + grp + 8};
    const int cols[2] = {n0 + ns * 8 + tig * 2, n0 + ns * 8 + tig * 2 + 1};
    const bool v[2] = {cols[0] < H, cols[1] < H};
    float br[2], bz[2], bn2[2];
#pragma unroll
    for (int j = 0; j < 2; j++) {
        br[j] = v[j] ? bhh[cols[j]] : 0.f;
        bz[j] = v[j] ? bhh[H + cols[j]] : 0.f;
        bn2[j] = v[j] ? bhh[2 * H + cols[j]] : 0.f;
    }
    float hreg[2][2] = {{0.f, 0.f}, {0.f, 0.f}};

    for (int t = 0; t < T; t++) {
        const float* gp = gsrc + (long)t * gstep;
        float ga[2][2][3];
#pragma unroll
        for (int i = 0; i < 2; i++) {
            const float* gr = gp + (long)rows[i] * H3;
#pragma unroll
            for (int j = 0; j < 2; j++) {
                ga[i][j][0] = v[j] ? gr[cols[j]] : 0.f;
                ga[i][j][1] = v[j] ? gr[H + cols[j]] : 0.f;
                ga[i][j][2] = v[j] ? gr[2 * H + cols[j]] : 0.f;
            }
        }

        float cf[3][4];
        if (t > 0) {
            run_tile(yhi + (long)(t - 1) * B * KPAD, ylo + (long)(t - 1) * B * KPAD,
                     m0, sb, cf);
        } else {
#pragma unroll
            for (int g = 0; g < 3; g++)
#pragma unroll
                for (int j = 0; j < 4; j++) cf[g][j] = 0.f;
        }

#pragma unroll
        for (int i = 0; i < 2; i++) {
            const long obase = ((long)t * B + rows[i]) * KPAD;
#pragma unroll
            for (int j = 0; j < 2; j++) {
                float h = 0.f;
                if (v[j]) {
                    const int reg = i * 2 + j;
                    const float r = sigm(ga[i][j][0] + cf[0][reg] + br[j]);
                    const float z = sigm(ga[i][j][1] + cf[1][reg] + bz[j]);
                    const float nn = tanhf(ga[i][j][2] + r * (cf[2][reg] + bn2[j]));
                    h = (1.f - z) * nn + z * hreg[i][j];
                }
                hreg[i][j] = h;
                const bf16 hh = __float2bfloat16(h);
                yhi[obase + cols[j]] = hh;
                ylo[obase + cols[j]] = __float2bfloat16(h - __bfloat162float(hh));
            }
        }
        grid_sync();
    }
}

// ---- batched input-gate GEMM: 1108 M-tiles over 128 blocks ----
__device__ void gate_layer(const bf16* __restrict__ yhi, const bf16* __restrict__ ylo,
                           const bf16* __restrict__ whi, const bf16* __restrict__ wlo,
                           const float* __restrict__ bih, float* __restrict__ G, u32 sb) {
    const int n0 = (blockIdx.x & 31) * 16;
    const int mt0 = blockIdx.x >> 5;
    const int tid = threadIdx.x;
    const int w = tid >> 5;
    const int mi = w >> 1;
    const int ns = w & 1;
    const int lane = tid & 31;
    const int grp = lane >> 2;
    const int tig = lane & 3;

    load_W(whi, wlo, n0);
    __syncthreads();

    const int cols[2] = {n0 + ns * 8 + tig * 2, n0 + ns * 8 + tig * 2 + 1};
    const bool v[2] = {cols[0] < H, cols[1] < H};
    float b0[2], b1[2], b2[2];
#pragma unroll
    for (int j = 0; j < 2; j++) {
        b0[j] = v[j] ? bih[cols[j]] : 0.f;
        b1[j] = v[j] ? bih[H + cols[j]] : 0.f;
        b2[j] = v[j] ? bih[2 * H + cols[j]] : 0.f;
    }

    for (int mt = mt0; mt < MT_GATE; mt += 4) {
        const int m0 = mt * 64;
        float cf[3][4];
        // FIX (R11): pass layer base pointers; run_tile/stage_chunk add m0 itself.
        run_tile(yhi, ylo, m0, sb, cf);
#pragma unroll
        for (int i = 0; i < 2; i++) {
            const long m = m0 + mi * 16 + grp + i * 8;
            float* gr = G + m * H3;
#pragma unroll
            for (int j = 0; j < 2; j++) {
                if (v[j]) {
                    const int reg = i * 2 + j;
                    gr[cols[j]] = cf[0][reg] + b0[j];
                    gr[H + cols[j]] = cf[1][reg] + b1[j];
                    gr[2 * H + cols[j]] = cf[2][reg] + b2[j];
                }
            }
        }
    }
}

// ---- fc2 + permute to (B, O, T) ----
__device__ void fc2_phase(const bf16* __restrict__ yhi, const bf16* __restrict__ ylo,
                          const float* __restrict__ W, const float* __restrict__ bias,
                          float* __restrict__ out) {
    const int wid = threadIdx.x >> 5;
    const int lane = threadIdx.x & 31;
    const int M = T * B;
    float* rows = (float*)smc;
    for (int base = blockIdx.x * 8; base < M; base += NBLK * 8) {
        const int row = base + wid;
        if (row < M) {
            for (int k = lane; k < H; k += 32)
                rows[wid * 502 + k] = __bfloat162float(yhi[(long)row * KPAD + k]) +
                                      __bfloat162float(ylo[(long)row * KPAD + k]);
            __syncwarp();
            const int t = row / B;
            const int b = row % B;
            for (int o = lane; o < O; o += 32) {
                float acc = bias[o];
                const float* wr = W + o * H;
                for (int k = 0; k < H; k++) acc += rows[wid * 502 + k] * wr[k];
                out[((long)b * O + o) * T + t] = acc;
            }
            __syncwarp();
        }
    }
}

// ---- persistent mega-kernel ----
__global__ void __launch_bounds__(NTHR, 1) decoder_kernel(
    const float* __restrict__ x,
    const float* __restrict__ fc1_w, const float* __restrict__ fc1_b,
    const float* __restrict__ w_ih0, const float* __restrict__ w_hh0,
    const float* __restrict__ b_ih0, const float* __restrict__ b_hh0,
    const float* __restrict__ w_ih1, const float* __restrict__ w_hh1,
    const float* __restrict__ b_ih1, const float* __restrict__ b_hh1,
    const float* __restrict__ w_ih2, const float* __restrict__ w_hh2,
    const float* __restrict__ b_ih2, const float* __restrict__ b_hh2,
    const float* __restrict__ fc2_w, const float* __restrict__ fc2_b,
    float* __restrict__ out) {
    const int tid = threadIdx.x;
    const u32 sb = s2u(smc);

    split_mat(w_hh0, d_whh[0][0], d_whh[0][1]);
    split_mat(w_hh1, d_whh[1][0], d_whh[1][1]);
    split_mat(w_hh2, d_whh[2][0], d_whh[2][1]);
    split_mat(w_ih1, d_wih[0][0], d_wih[0][1]);
    split_mat(w_ih2, d_wih[1][0], d_wih[1][1]);

    const int gt = blockIdx.x * NTHR + tid;
    const int GT = NBLK * NTHR;
    for (int i = gt; i < B * D; i += GT) {
        const int b = i / D, d = i % D;
        float acc = fc1_b[d];
        for (int k = 0; k < D; k++) acc += x[b * D + k] * fc1_w[d * D + k];
        d_hin[i] = fmaxf(acc, 0.f);
    }
    grid_sync();
    for (int i = gt; i < B * H3; i += GT) {
        const int b = i / H3, j = i % H3;
        float acc = b_ih0[j];
        for (int k = 0; k < D; k++) acc += d_hin[b * D + k] * w_ih0[j * D + k];
        d_g0[i] = acc;
    }
    grid_sync();

    scan_layer(d_g0, 0, d_whh[0][0], d_whh[0][1], b_hh0, d_yAhi, d_yAlo, sb);
    gate_layer(d_yAhi, d_yAlo, d_wih[0][0], d_wih[0][1], b_ih1, d_gbuf, sb);
    grid_sync();
    scan_layer(d_gbuf, (long)B * H3, d_whh[1][0], d_whh[1][1], b_hh1, d_yBhi, d_yBlo, sb);
    gate_layer(d_yBhi, d_yBlo, d_wih[1][0], d_wih[1][1], b_ih2, d_gbuf, sb);
    grid_sync();
    scan_layer(d_gbuf, (long)B * H3, d_whh[2][0], d_whh[2][1], b_hh2, d_yAhi, d_yAlo, sb);

    fc2_phase(d_yAhi, d_yAlo, fc2_w, fc2_b, out);
}

extern "C" void kernel_launch(void* const* d_in, const int* in_sizes, int n_in,
                              void* d_out, int out_size) {
    const float* x     = (const float*)d_in[0];
    const float* fc1_w = (const float*)d_in[1];
    const float* fc1_b = (const float*)d_in[2];
    const float* w_ih0 = (const float*)d_in[3];
    const float* w_hh0 = (const float*)d_in[4];
    const float* b_ih0 = (const float*)d_in[5];
    const float* b_hh0 = (const float*)d_in[6];
    const float* w_ih1 = (const float*)d_in[7];
    const float* w_hh1 = (const float*)d_in[8];
    const float* b_ih1 = (const float*)d_in[9];
    const float* b_hh1 = (const float*)d_in[10];
    const float* w_ih2 = (const float*)d_in[11];
    const float* w_hh2 = (const float*)d_in[12];
    const float* b_ih2 = (const float*)d_in[13];
    const float* b_hh2 = (const float*)d_in[14];
    const float* fc2_w = (const float*)d_in[15];
    const float* fc2_b = (const float*)d_in[16];
    float* out = (float*)d_out;

    cudaFuncSetAttribute(decoder_kernel, cudaFuncAttributeMaxDynamicSharedMemorySize,
                         SMEM_BYTES);
    decoder_kernel<<<NBLK, NTHR, SMEM_BYTES>>>(x, fc1_w, fc1_b,
                                               w_ih0, w_hh0, b_ih0, b_hh0,
                                               w_ih1, w_hh1, b_ih1, b_hh1,
                                               w_ih2, w_hh2, b_ih2, b_hh2,
                                               fc2_w, fc2_b, out);
}

// round 13
// speedup vs baseline: 2.8632x; 1.0090x over previous
#include <cuda_runtime.h>
#include <cuda_bf16.h>
#include <math.h>
#include <stdint.h>

#define D 56
#define H 501
#define T 277
#define O 76
#define B 256
#define H3 1503
#define NBLK 128
#define NTHR 512
#define KPAD 512
#define MT_GATE 1108

typedef unsigned long long ull;
typedef uint32_t u32;
typedef __nv_bfloat16 bf16;

// ---- smem layout (bytes) ----
#define WSTRB 1040
#define WHI_OFF 0
#define WLO_OFF 49920
#define ASTRB 144                 /* 64 bf16 (128B) + 16 pad */
#define ABUF_HI 9216              /* 64 rows * 144 */
#define ABUF_SZ 18432             /* hi + lo */
#define ABUF_OFF 99840
#define AWG_STRIDE 36864          /* 2 bufs per warpgroup */
#define SMEM_BYTES (ABUF_OFF + 2 * AWG_STRIDE)   /* 173568 */

extern __shared__ char smc[];

// ---- static device scratch ----
__device__ float d_hin[B * D];
__device__ float d_g0[B * H3];
__device__ float d_gbuf[(long)T * B * H3];
__device__ bf16 d_yAhi[(long)T * B * KPAD], d_yAlo[(long)T * B * KPAD];
__device__ bf16 d_yBhi[(long)T * B * KPAD], d_yBlo[(long)T * B * KPAD];
__device__ bf16 d_whh[3][2][H3 * KPAD];
__device__ bf16 d_wih[2][2][H3 * KPAD];

// ---- grid barrier ----
__device__ unsigned int g_arrive = 0;
__device__ volatile unsigned int g_gen = 0;
__device__ __forceinline__ void grid_sync() {
    __syncthreads();
    if (threadIdx.x == 0) {
        __threadfence();
        unsigned int gen = g_gen;
        if (atomicAdd(&g_arrive, 1u) == (unsigned)(NBLK - 1)) {
            g_arrive = 0;
            __threadfence();
            g_gen = gen + 1;
        } else {
            while (g_gen == gen) { }
        }
        __threadfence();
    }
    __syncthreads();
}

// ---- PTX helpers ----
__device__ __forceinline__ u32 s2u(const void* p) {
    u32 a;
    asm("{ .reg .u64 t; cvta.to.shared.u64 t, %1; cvt.u32.u64 %0, t; }" : "=r"(a) : "l"(p));
    return a;
}
#define LDSM_X4(r0, r1, r2, r3, a) \
    asm volatile("ldmatrix.sync.aligned.m8n8.x4.shared.b16 {%0,%1,%2,%3}, [%4];" \
                 : "=r"(r0), "=r"(r1), "=r"(r2), "=r"(r3) : "r"(a))
#define LDSM_X2(r0, r1, a) \
    asm volatile("ldmatrix.sync.aligned.m8n8.x2.shared.b16 {%0,%1}, [%2];" \
                 : "=r"(r0), "=r"(r1) : "r"(a))
#define CP_ASYNC(sdst, gsrc) \
    asm volatile("cp.async.cg.shared.global [%0], [%1], 16;" :: "r"(sdst), "l"(gsrc))
#define CP_COMMIT() asm volatile("cp.async.commit_group;" ::: "memory")
#define CP_WAIT1() asm volatile("cp.async.wait_group 1;" ::: "memory")
#define CP_WAIT0() asm volatile("cp.async.wait_group 0;" ::: "memory")
#define BARWG(wg) asm volatile("bar.sync %0, 256;" :: "r"((wg) + 1) : "memory")

__device__ __forceinline__ void hmma(float c[4], const u32 a[4], u32 b0, u32 b1) {
    asm volatile(
        "mma.sync.aligned.m16n8k16.row.col.f32.bf16.bf16.f32 "
        "{%0,%1,%2,%3}, {%4,%5,%6,%7}, {%8,%9}, {%0,%1,%2,%3};"
        : "+f"(c[0]), "+f"(c[1]), "+f"(c[2]), "+f"(c[3])
        : "r"(a[0]), "r"(a[1]), "r"(a[2]), "r"(a[3]), "r"(b0), "r"(b1));
}

__device__ __forceinline__ float sigm(float x) { return 1.f / (1.f + __expf(-x)); }

// ---- weight hi/lo split precompute ----
__device__ void split_mat(const float* __restrict__ w, bf16* __restrict__ hi,
                          bf16* __restrict__ lo) {
    const long n = (long)H3 * KPAD;
    for (long i = (long)blockIdx.x * NTHR + threadIdx.x; i < n; i += (long)NBLK * NTHR) {
        const int r = (int)(i >> 9);
        const int k = (int)(i & (KPAD - 1));
        const float v = (k < H) ? w[(long)r * H + k] : 0.f;
        const bf16 h = __float2bfloat16(v);
        hi[i] = h;
        lo[i] = __float2bfloat16(v - __bfloat162float(h));
    }
}

// ---- load W hi+lo tile into smem ----
__device__ void load_W(const bf16* __restrict__ whi, const bf16* __restrict__ wlo, int n0) {
    for (int idx = threadIdx.x; idx < 3072; idx += NTHR) {
        const int r = idx >> 6;
        const int seg = idx & 63;
        const int g = r >> 4;
        const int n = n0 + (r & 15);
        uint4 vh = make_uint4(0, 0, 0, 0), vl = vh;
        if (n < H) {
            const long off = (long)(g * H + n) * KPAD + seg * 8;
            vh = *(const uint4*)(whi + off);
            vl = *(const uint4*)(wlo + off);
        }
        const u32 so = (u32)r * WSTRB + seg * 16;
        *(uint4*)(smc + WHI_OFF + so) = vh;
        *(uint4*)(smc + WLO_OFF + so) = vl;
    }
}

// ---- stage one 64x64 A chunk (hi+lo) for one warpgroup ----
__device__ __forceinline__ void stage_chunk(const bf16* __restrict__ ahi,
                                            const bf16* __restrict__ alo,
                                            int m0, int wg, int c, u32 sA, int wtid) {
#pragma unroll
    for (int i = 0; i < 2; i++) {
        const int idx = wtid + i * 256;
        const int row = idx >> 3;
        const int seg = idx & 7;
        const long go = (long)(m0 + row) * KPAD + wg * 256 + c * 64 + seg * 8;
        const u32 so = (u32)row * ASTRB + seg * 16;
        CP_ASYNC(sA + so, ahi + go);
        CP_ASYNC(sA + ABUF_HI + so, alo + go);
    }
}

// ---- 64x48x512 tile, split-K across 2 warpgroups, 3-term bf16 compensation ----
// cf valid in warpgroup 0 after return.
__device__ void run_tile(const bf16* __restrict__ ahi, const bf16* __restrict__ alo,
                         int m0, u32 sb, float cf[3][4]) {
    const int tid = threadIdx.x;
    const int wg = tid >> 8;
    const int wtid = tid & 255;
    const int w = wtid >> 5;
    const int mi = w >> 1;
    const int ns = w & 1;
    const int lane = tid & 31;

#pragma unroll
    for (int g = 0; g < 3; g++)
#pragma unroll
        for (int j = 0; j < 4; j++) cf[g][j] = 0.f;

    const u32 aoff = (u32)(mi * 16 + (lane & 15)) * ASTRB + (lane >> 4) * 16;
    const int gsel = lane >> 4;
    const int khalf = (lane >> 3) & 1;
    const u32 b01off = (u32)(gsel * 16 + ns * 8 + (lane & 7)) * WSTRB + khalf * 16;
    const int l2 = lane & 15;
    const u32 b2off = (u32)(32 + ns * 8 + (l2 & 7)) * WSTRB + (l2 >> 3) * 16;
    const u32 abase = sb + ABUF_OFF + wg * AWG_STRIDE;
    const u32 kwg = wg * 512;   // byte offset of this wg's k-range within a W row

    stage_chunk(ahi, alo, m0, wg, 0, abase, wtid);
    CP_COMMIT();

#pragma unroll 1
    for (int c = 0; c < 4; c++) {
        if (c < 3) {
            stage_chunk(ahi, alo, m0, wg, c + 1, abase + ((c + 1) & 1) * ABUF_SZ, wtid);
            CP_COMMIT();
            CP_WAIT1();
        } else {
            CP_WAIT0();
        }
        BARWG(wg);

        const u32 aH = abase + (c & 1) * ABUF_SZ + aoff;
        const u32 aL = aH + ABUF_HI;
        const u32 co = kwg + c * 128;
        const u32 bH01 = sb + WHI_OFF + b01off + co;
        const u32 bH2 = sb + WHI_OFF + b2off + co;
        const u32 bL01 = sb + WLO_OFF + b01off + co;
        const u32 bL2 = sb + WLO_OFF + b2off + co;

#pragma unroll
        for (int kk = 0; kk < 4; kk++) {
            const u32 ko = kk * 32;
            u32 ah[4], al[4], bh[4], bh2[2], bl[4], bl2[2];
            LDSM_X4(ah[0], ah[1], ah[2], ah[3], aH + ko);
            LDSM_X4(al[0], al[1], al[2], al[3], aL + ko);
            LDSM_X4(bh[0], bh[1], bh[2], bh[3], bH01 + ko);
            LDSM_X2(bh2[0], bh2[1], bH2 + ko);
            LDSM_X4(bl[0], bl[1], bl[2], bl[3], bL01 + ko);
            LDSM_X2(bl2[0], bl2[1], bL2 + ko);
            hmma(cf[0], ah, bh[0], bh[1]);
            hmma(cf[1], ah, bh[2], bh[3]);
            hmma(cf[2], ah, bh2[0], bh2[1]);
            hmma(cf[0], al, bh[0], bh[1]);
            hmma(cf[1], al, bh[2], bh[3]);
            hmma(cf[2], al, bh2[0], bh2[1]);
            hmma(cf[0], ah, bl[0], bl[1]);
            hmma(cf[1], ah, bl[2], bl[3]);
            hmma(cf[2], ah, bl2[0], bl2[1]);
        }
        BARWG(wg);
    }

    // cross-warpgroup reduction: wg1 -> smem -> wg0
    float* red = (float*)(smc + ABUF_OFF);
    __syncthreads();
    if (wg == 1) {
#pragma unroll
        for (int g = 0; g < 3; g++)
#pragma unroll
            for (int j = 0; j < 4; j++) red[wtid * 12 + g * 4 + j] = cf[g][j];
    }
    __syncthreads();
    if (wg == 0) {
#pragma unroll
        for (int g = 0; g < 3; g++)
#pragma unroll
            for (int j = 0; j < 4; j++) cf[g][j] += red[wtid * 12 + g * 4 + j];
    }
    __syncthreads();   // protect red area before next tile's staging
}

// ---- GRU layer scan: h carried in registers (warpgroup 0) ----
__device__ void scan_layer(const float* __restrict__ gsrc, long gstep,
                           const bf16* __restrict__ whi, const bf16* __restrict__ wlo,
                           const float* __restrict__ bhh,
                           bf16* __restrict__ yhi, bf16* __restrict__ ylo, u32 sb) {
    const int m0 = (blockIdx.x >> 5) * 64;
    const int n0 = (blockIdx.x & 31) * 16;
    const int tid = threadIdx.x;
    const bool wg0 = tid < 256;
    const int w = (tid & 255) >> 5;
    const int mi = w >> 1;
    const int ns = w & 1;
    const int lane = tid & 31;
    const int grp = lane >> 2;
    const int tig = lane & 3;

    load_W(whi, wlo, n0);
    __syncthreads();

    const int rows[2] = {m0 + mi * 16 + grp, m0 + mi * 16 + grp + 8};
    const int cols[2] = {n0 + ns * 8 + tig * 2, n0 + ns * 8 + tig * 2 + 1};
    const bool v[2] = {cols[0] < H, cols[1] < H};
    float br[2], bz[2], bn2[2];
#pragma unroll
    for (int j = 0; j < 2; j++) {
        br[j] = v[j] ? bhh[cols[j]] : 0.f;
        bz[j] = v[j] ? bhh[H + cols[j]] : 0.f;
        bn2[j] = v[j] ? bhh[2 * H + cols[j]] : 0.f;
    }
    float hreg[2][2] = {{0.f, 0.f}, {0.f, 0.f}};

    for (int t = 0; t < T; t++) {
        float ga[2][2][3];
        if (wg0) {
            const float* gp = gsrc + (long)t * gstep;
#pragma unroll
            for (int i = 0; i < 2; i++) {
                const float* gr = gp + (long)rows[i] * H3;
#pragma unroll
                for (int j = 0; j < 2; j++) {
                    ga[i][j][0] = v[j] ? gr[cols[j]] : 0.f;
                    ga[i][j][1] = v[j] ? gr[H + cols[j]] : 0.f;
                    ga[i][j][2] = v[j] ? gr[2 * H + cols[j]] : 0.f;
                }
            }
        }

        float cf[3][4];
        if (t > 0) {
            run_tile(yhi + (long)(t - 1) * B * KPAD, ylo + (long)(t - 1) * B * KPAD,
                     m0, sb, cf);
        } else {
#pragma unroll
            for (int g = 0; g < 3; g++)
#pragma unroll
                for (int j = 0; j < 4; j++) cf[g][j] = 0.f;
        }

        if (wg0) {
#pragma unroll
            for (int i = 0; i < 2; i++) {
                const long obase = ((long)t * B + rows[i]) * KPAD;
#pragma unroll
                for (int j = 0; j < 2; j++) {
                    float h = 0.f;
                    if (v[j]) {
                        const int reg = i * 2 + j;
                        const float r = sigm(ga[i][j][0] + cf[0][reg] + br[j]);
                        const float z = sigm(ga[i][j][1] + cf[1][reg] + bz[j]);
                        const float nn = tanhf(ga[i][j][2] + r * (cf[2][reg] + bn2[j]));
                        h = (1.f - z) * nn + z * hreg[i][j];
                    }
                    hreg[i][j] = h;
                    const bf16 hh = __float2bfloat16(h);
                    yhi[obase + cols[j]] = hh;
                    ylo[obase + cols[j]] = __float2bfloat16(h - __bfloat162float(hh));
                }
            }
        }
        grid_sync();
    }
}

// ---- batched input-gate GEMM ----
__device__ void gate_layer(const bf16* __restrict__ yhi, const bf16* __restrict__ ylo,
                           const bf16* __restrict__ whi, const bf16* __restrict__ wlo,
                           const float* __restrict__ bih, float* __restrict__ G, u32 sb) {
    const int n0 = (blockIdx.x & 31) * 16;
    const int mt0 = blockIdx.x >> 5;
    const int tid = threadIdx.x;
    const bool wg0 = tid < 256;
    const int w = (tid & 255) >> 5;
    const int mi = w >> 1;
    const int ns = w & 1;
    const int lane = tid & 31;
    const int grp = lane >> 2;
    const int tig = lane & 3;

    load_W(whi, wlo, n0);
    __syncthreads();

    const int cols[2] = {n0 + ns * 8 + tig * 2, n0 + ns * 8 + tig * 2 + 1};
    const bool v[2] = {cols[0] < H, cols[1] < H};
    float b0[2], b1[2], b2[2];
#pragma unroll
    for (int j = 0; j < 2; j++) {
        b0[j] = v[j] ? bih[cols[j]] : 0.f;
        b1[j] = v[j] ? bih[H + cols[j]] : 0.f;
        b2[j] = v[j] ? bih[2 * H + cols[j]] : 0.f;
    }

    for (int mt = mt0; mt < MT_GATE; mt += 4) {
        const int m0 = mt * 64;
        float cf[3][4];
        run_tile(yhi, ylo, m0, sb, cf);
        if (wg0) {
#pragma unroll
            for (int i = 0; i < 2; i++) {
                const long m = m0 + mi * 16 + grp + i * 8;
                float* gr = G + m * H3;
#pragma unroll
                for (int j = 0; j < 2; j++) {
                    if (v[j]) {
                        const int reg = i * 2 + j;
                        gr[cols[j]] = cf[0][reg] + b0[j];
                        gr[H + cols[j]] = cf[1][reg] + b1[j];
                        gr[2 * H + cols[j]] = cf[2][reg] + b2[j];
                    }
                }
            }
        }
    }
}

// ---- fc2 + permute to (B, O, T) ----
__device__ void fc2_phase(const bf16* __restrict__ yhi, const bf16* __restrict__ ylo,
                          const float* __restrict__ W, const float* __restrict__ bias,
                          float* __restrict__ out) {
    const int wid = threadIdx.x >> 5;   // 0..15
    const int lane = threadIdx.x & 31;
    const int M = T * B;
    float* rows = (float*)smc;          // 16 x 502 floats
    for (int base = blockIdx.x * 16; base < M; base += NBLK * 16) {
        const int row = base + wid;
        if (row < M) {
            for (int k = lane; k < H; k += 32)
                rows[wid * 502 + k] = __bfloat162float(yhi[(long)row * KPAD + k]) +
                                      __bfloat162float(ylo[(long)row * KPAD + k]);
            __syncwarp();
            const int t = row / B;
            const int b = row % B;
            for (int o = lane; o < O; o += 32) {
                float acc = bias[o];
                const float* wr = W + o * H;
                for (int k = 0; k < H; k++) acc += rows[wid * 502 + k] * wr[k];
                out[((long)b * O + o) * T + t] = acc;
            }
            __syncwarp();
        }
    }
}

// ---- persistent mega-kernel ----
__global__ void __launch_bounds__(NTHR, 1) decoder_kernel(
    const float* __restrict__ x,
    const float* __restrict__ fc1_w, const float* __restrict__ fc1_b,
    const float* __restrict__ w_ih0, const float* __restrict__ w_hh0,
    const float* __restrict__ b_ih0, const float* __restrict__ b_hh0,
    const float* __restrict__ w_ih1, const float* __restrict__ w_hh1,
    const float* __restrict__ b_ih1, const float* __restrict__ b_hh1,
    const float* __restrict__ w_ih2, const float* __restrict__ w_hh2,
    const float* __restrict__ b_ih2, const float* __restrict__ b_hh2,
    const float* __restrict__ fc2_w, const float* __restrict__ fc2_b,
    float* __restrict__ out) {
    const int tid = threadIdx.x;
    const u32 sb = s2u(smc);

    split_mat(w_hh0, d_whh[0][0], d_whh[0][1]);
    split_mat(w_hh1, d_whh[1][0], d_whh[1][1]);
    split_mat(w_hh2, d_whh[2][0], d_whh[2][1]);
    split_mat(w_ih1, d_wih[0][0], d_wih[0][1]);
    split_mat(w_ih2, d_wih[1][0], d_wih[1][1]);

    const int gt = blockIdx.x * NTHR + tid;
    const int GT = NBLK * NTHR;
    for (int i = gt; i < B * D; i += GT) {
        const int b = i / D, d = i % D;
        float acc = fc1_b[d];
        for (int k = 0; k < D; k++) acc += x[b * D + k] * fc1_w[d * D + k];
        d_hin[i] = fmaxf(acc, 0.f);
    }
    grid_sync();
    for (int i = gt; i < B * H3; i += GT) {
        const int b = i / H3, j = i % H3;
        float acc = b_ih0[j];
        for (int k = 0; k < D; k++) acc += d_hin[b * D + k] * w_ih0[j * D + k];
        d_g0[i] = acc;
    }
    grid_sync();

    scan_layer(d_g0, 0, d_whh[0][0], d_whh[0][1], b_hh0, d_yAhi, d_yAlo, sb);
    gate_layer(d_yAhi, d_yAlo, d_wih[0][0], d_wih[0][1], b_ih1, d_gbuf, sb);
    grid_sync();
    scan_layer(d_gbuf, (long)B * H3, d_whh[1][0], d_whh[1][1], b_hh1, d_yBhi, d_yBlo, sb);
    gate_layer(d_yBhi, d_yBlo, d_wih[1][0], d_wih[1][1], b_ih2, d_gbuf, sb);
    grid_sync();
    scan_layer(d_gbuf, (long)B * H3, d_whh[2][0], d_whh[2][1], b_hh2, d_yAhi, d_yAlo, sb);

    fc2_phase(d_yAhi, d_yAlo, fc2_w, fc2_b, out);
}

extern "C" void kernel_launch(void* const* d_in, const int* in_sizes, int n_in,
                              void* d_out, int out_size) {
    const float* x     = (const float*)d_in[0];
    const float* fc1_w = (const float*)d_in[1];
    const float* fc1_b = (const float*)d_in[2];
    const float* w_ih0 = (const float*)d_in[3];
    const float* w_hh0 = (const float*)d_in[4];
    const float* b_ih0 = (const float*)d_in[5];
    const float* b_hh0 = (const float*)d_in[6];
    const float* w_ih1 = (const float*)d_in[7];
    const float* w_hh1 = (const float*)d_in[8];
    const float* b_ih1 = (const float*)d_in[9];
    const float* b_hh1 = (const float*)d_in[10];
    const float* w_ih2 = (const float*)d_in[11];
    const float* w_hh2 = (const float*)d_in[12];
    const float* b_ih2 = (const float*)d_in[13];
    const float* b_hh2 = (const float*)d_in[14];
    const float* fc2_w = (const float*)d_in[15];
    const float* fc2_b = (const float*)d_in[16];
    float* out = (float*)d_out;

    cudaFuncSetAttribute(decoder_kernel, cudaFuncAttributeMaxDynamicSharedMemorySize,
                         SMEM_BYTES);
    decoder_kernel<<<NBLK, NTHR, SMEM_BYTES>>>(x, fc1_w, fc1_b,
                                               w_ih0, w_hh0, b_ih0, b_hh0,
                                               w_ih1, w_hh1, b_ih1, b_hh1,
                                               w_ih2, w_hh2, b_ih2, b_hh2,
                                               fc2_w, fc2_b, out);
}